// round 2
// baseline (speedup 1.0000x reference)
#include <cuda_runtime.h>
#include <cuda_bf16.h>
#include <math.h>

// ---------------- problem constants ----------------
#define NN      20000
#define EDG     320000
#define ETOT    (EDG + NN)      // edges + self loops
#define FIN     512
#define HC12    256             // 4 heads * 64
#define HC3     64
#define NGRAPH  64
#define NCLASS  5
#define SLOPE   0.2f
#define EPS_BN  1e-5f

// ---------------- device scratch (static, no runtime alloc) ----------------
__device__ float g_hlin[(size_t)NN * HC12];   // GEMM output per layer
__device__ float g_hagg[(size_t)NN * HC12];   // aggregated (layer output)
__device__ float g_als[NN * 4];
__device__ float g_ald[NN * 4];
__device__ float g_ee[(size_t)ETOT * 4];
__device__ float g_denom[NN * 4];
__device__ int   g_counts[NN];
__device__ int   g_cursor[NN];
__device__ int   g_rowptr[NN + 1];
__device__ int   g_csr_src[ETOT];
__device__ int   g_csr_eid[ETOT];
__device__ float g_pooled[NGRAPH * HC3];
__device__ int   g_cnt[NGRAPH];

// ---------------- utility kernels ----------------
__global__ void fill_zero_f(float* p, int n) {
    int i = blockIdx.x * blockDim.x + threadIdx.x;
    if (i < n) p[i] = 0.0f;
}
__global__ void fill_zero_i(int* p, int n) {
    int i = blockIdx.x * blockDim.x + threadIdx.x;
    if (i < n) p[i] = 0;
}

// ---------------- CSR build ----------------
__global__ void hist_kernel(const int* __restrict__ ei, int* __restrict__ counts) {
    int e = blockIdx.x * blockDim.x + threadIdx.x;
    if (e >= ETOT) return;
    int d = (e < EDG) ? ei[EDG + e] : (e - EDG);
    atomicAdd(&counts[d], 1);
}

// single-block exclusive scan over NN counts -> rowptr
__global__ void scan_kernel(const int* __restrict__ counts, int* __restrict__ rowptr) {
    __shared__ int sh[1024];
    __shared__ int carry;
    int t = threadIdx.x;
    if (t == 0) { carry = 0; rowptr[0] = 0; }
    __syncthreads();
    for (int base = 0; base < NN; base += 1024) {
        int i = base + t;
        int v = (i < NN) ? counts[i] : 0;
        sh[t] = v;
        __syncthreads();
        for (int off = 1; off < 1024; off <<= 1) {
            int tv = (t >= off) ? sh[t - off] : 0;
            __syncthreads();
            sh[t] += tv;
            __syncthreads();
        }
        int incl = sh[t] + carry;
        if (i < NN) rowptr[i + 1] = incl;
        __syncthreads();
        if (t == 1023) carry = incl;
        __syncthreads();
    }
}

__global__ void scatter_kernel(const int* __restrict__ ei,
                               const int* __restrict__ rowptr,
                               int* __restrict__ cursor,
                               int* __restrict__ csr_src,
                               int* __restrict__ csr_eid) {
    int e = blockIdx.x * blockDim.x + threadIdx.x;
    if (e >= ETOT) return;
    int s, d;
    if (e < EDG) { s = ei[e]; d = ei[EDG + e]; }
    else         { s = d = e - EDG; }
    int pos = rowptr[d] + atomicAdd(&cursor[d], 1);
    csr_src[pos] = s;
    csr_eid[pos] = e;
}

// ---------------- FP32 tiled GEMM: C[M,N] = A[M,K] * B[K,N], row-major ----------------
#define BM 64
#define BN 64
#define BK 16
__global__ void sgemm_kernel(const float* __restrict__ A, const float* __restrict__ B,
                             float* __restrict__ C, int M, int N, int K) {
    __shared__ float As[BK][BM + 1];
    __shared__ float Bs[BK][BN + 1];
    int bx = blockIdx.x * BN, by = blockIdx.y * BM;
    int tid = threadIdx.x;
    int tcol = tid & 15, trow = tid >> 4;
    float acc[4][4] = {};
    for (int k0 = 0; k0 < K; k0 += BK) {
#pragma unroll
        for (int i = 0; i < 4; i++) {
            int idx = tid + i * 256;
            int r = idx / BK, c = idx % BK;
            int gr = by + r;
            float v = 0.0f;
            if (gr < M) v = A[(size_t)gr * K + (k0 + c)];
            As[c][r] = v;
        }
#pragma unroll
        for (int i = 0; i < 4; i++) {
            int idx = tid + i * 256;
            int r = idx / BN, c = idx % BN;
            int gc = bx + c;
            float v = 0.0f;
            if (gc < N) v = B[(size_t)(k0 + r) * N + gc];
            Bs[r][c] = v;
        }
        __syncthreads();
#pragma unroll
        for (int kk = 0; kk < BK; kk++) {
            float a[4], b[4];
#pragma unroll
            for (int i = 0; i < 4; i++) a[i] = As[kk][trow * 4 + i];
#pragma unroll
            for (int j = 0; j < 4; j++) b[j] = Bs[kk][tcol * 4 + j];
#pragma unroll
            for (int i = 0; i < 4; i++)
#pragma unroll
                for (int j = 0; j < 4; j++) acc[i][j] += a[i] * b[j];
        }
        __syncthreads();
    }
#pragma unroll
    for (int i = 0; i < 4; i++) {
        int gr = by + trow * 4 + i;
        if (gr >= M) continue;
#pragma unroll
        for (int j = 0; j < 4; j++) {
            int gc = bx + tcol * 4 + j;
            if (gc < N) C[(size_t)gr * N + gc] = acc[i][j];
        }
    }
}

// ---------------- attention logits: warp per node ----------------
// a_src flattened over (head, channel) coincides exactly with the channel index of h.
template <int HCv, int Hv>
__global__ void attn_logits_kernel(const float* __restrict__ h,
                                   const float* __restrict__ a_s,
                                   const float* __restrict__ a_d,
                                   float* __restrict__ al_s,
                                   float* __restrict__ al_d) {
    int gw = (blockIdx.x * blockDim.x + threadIdx.x) >> 5;
    int lane = threadIdx.x & 31;
    if (gw >= NN) return;
    const int J = HCv / 32;
    float as_acc[Hv], ad_acc[Hv];
#pragma unroll
    for (int hh = 0; hh < Hv; hh++) { as_acc[hh] = 0.f; ad_acc[hh] = 0.f; }
    const float* hp = h + (size_t)gw * HCv;
#pragma unroll
    for (int j = 0; j < J; j++) {
        int c = lane + 32 * j;
        float v = hp[c];
        int hh = c >> 6;   // 64 channels per head
        as_acc[hh] += v * a_s[c];
        ad_acc[hh] += v * a_d[c];
    }
#pragma unroll
    for (int hh = 0; hh < Hv; hh++) {
        float s = as_acc[hh], d = ad_acc[hh];
#pragma unroll
        for (int off = 16; off; off >>= 1) {
            s += __shfl_down_sync(0xffffffffu, s, off);
            d += __shfl_down_sync(0xffffffffu, d, off);
        }
        if (lane == 0) {
            al_s[gw * Hv + hh] = s;
            al_d[gw * Hv + hh] = d;
        }
    }
}

// ---------------- edge softmax numerator + denominator (no max pass needed) ----------------
template <int Hv>
__global__ void edge_exp_kernel(const int* __restrict__ ei,
                                const float* __restrict__ al_s,
                                const float* __restrict__ al_d,
                                float* __restrict__ ee,
                                float* __restrict__ denom) {
    int e = blockIdx.x * blockDim.x + threadIdx.x;
    if (e >= ETOT) return;
    int s, d;
    if (e < EDG) { s = ei[e]; d = ei[EDG + e]; }
    else         { s = d = e - EDG; }
#pragma unroll
    for (int hh = 0; hh < Hv; hh++) {
        float v = al_s[s * Hv + hh] + al_d[d * Hv + hh];
        v = (v > 0.f) ? v : SLOPE * v;
        float w = __expf(v);
        ee[(size_t)e * Hv + hh] = w;
        atomicAdd(&denom[d * Hv + hh], w);
    }
}

// ---------------- aggregation (warp per dst node), fused bias [+ BN] + ReLU ----------------
// MODE 0: bias + BN + ReLU (layers 1,2). MODE 1: bias + ReLU (layer 3).
template <int HCv, int Hv, int MODE>
__global__ void gat_aggregate_kernel(const float* __restrict__ hlin,
                                     const int* __restrict__ rowptr,
                                     const int* __restrict__ csr_src,
                                     const int* __restrict__ csr_eid,
                                     const float* __restrict__ ee,
                                     const float* __restrict__ denom,
                                     const float* __restrict__ bias,
                                     const float* __restrict__ gamma,
                                     const float* __restrict__ beta,
                                     const float* __restrict__ mean,
                                     const float* __restrict__ var,
                                     float* __restrict__ out) {
    int gw = (blockIdx.x * blockDim.x + threadIdx.x) >> 5;
    int lane = threadIdx.x & 31;
    if (gw >= NN) return;
    const int CPL = HCv / 32;                 // 8 or 2 channels per lane
    int head = (lane * CPL) >> 6;             // 64 channels per head
    float acc[CPL];
#pragma unroll
    for (int j = 0; j < CPL; j++) acc[j] = 0.f;

    int beg = rowptr[gw], end = rowptr[gw + 1];
    for (int p = beg; p < end; p++) {
        int src = csr_src[p];
        int eid = csr_eid[p];
        float w = ee[(size_t)eid * Hv + head];
        const float* hp = hlin + (size_t)src * HCv + lane * CPL;
        if (CPL == 8) {
            const float4* hp4 = reinterpret_cast<const float4*>(hp);
            float4 v0 = hp4[0], v1 = hp4[1];
            acc[0] += w * v0.x; acc[1] += w * v0.y; acc[2] += w * v0.z; acc[3] += w * v0.w;
            acc[4] += w * v1.x; acc[5] += w * v1.y; acc[6] += w * v1.z; acc[7] += w * v1.w;
        } else {
            const float2* hp2 = reinterpret_cast<const float2*>(hp);
            float2 v = hp2[0];
            acc[0] += w * v.x; acc[1] += w * v.y;
        }
    }
    float inv = 1.0f / (denom[gw * Hv + head] + 1e-16f);
#pragma unroll
    for (int j = 0; j < CPL; j++) {
        int c = lane * CPL + j;
        float v = acc[j] * inv + bias[c];
        if (MODE == 0) {
            v = (v - mean[c]) * rsqrtf(var[c] + EPS_BN) * gamma[c] + beta[c];
        }
        v = (v > 0.f) ? v : 0.f;
        out[(size_t)gw * HCv + c] = v;
    }
}

// ---------------- mean pool (warp per node) ----------------
__global__ void pool_kernel(const float* __restrict__ h, const int* __restrict__ batch,
                            float* __restrict__ pooled, int* __restrict__ cnt) {
    int gw = (blockIdx.x * blockDim.x + threadIdx.x) >> 5;
    int lane = threadIdx.x & 31;
    if (gw >= NN) return;
    int b = batch[gw];
#pragma unroll
    for (int j = 0; j < 2; j++) {
        int c = lane + 32 * j;
        atomicAdd(&pooled[b * HC3 + c], h[(size_t)gw * HC3 + c]);
    }
    if (lane == 0) atomicAdd(&cnt[b], 1);
}

// ---------------- final MLP: block per graph ----------------
__global__ void mlp_kernel(const float* __restrict__ pooled, const int* __restrict__ cnt,
                           const float* __restrict__ w1, const float* __restrict__ b1,
                           const float* __restrict__ w2, const float* __restrict__ b2,
                           float* __restrict__ out) {
    int g = blockIdx.x;
    int t = threadIdx.x;        // 64 threads
    __shared__ float m[HC3];
    __shared__ float hid[32];
    float c = (float)cnt[g];
    if (c < 1.0f) c = 1.0f;
    m[t] = pooled[g * HC3 + t] / c;
    __syncthreads();
    if (t < 32) {
        float s = b1[t];
#pragma unroll
        for (int k = 0; k < HC3; k++) s += m[k] * w1[k * 32 + t];
        hid[t] = (s > 0.f) ? s : 0.f;
    }
    __syncthreads();
    if (t < NCLASS) {
        float s = b2[t];
#pragma unroll
        for (int k = 0; k < 32; k++) s += hid[k] * w2[k * NCLASS + t];
        out[g * NCLASS + t] = s;
    }
}

// ---------------- host orchestration ----------------
static inline int cdiv(int a, int b) { return (a + b - 1) / b; }

extern "C" void kernel_launch(void* const* d_in, const int* in_sizes, int n_in,
                              void* d_out, int out_size) {
    const float* x        = (const float*)d_in[0];
    const int*   ei       = (const int*)  d_in[1];
    const int*   batch    = (const int*)  d_in[2];
    const float* W1       = (const float*)d_in[3];
    const float* a1s      = (const float*)d_in[4];
    const float* a1d      = (const float*)d_in[5];
    const float* b1       = (const float*)d_in[6];
    const float* bn1g     = (const float*)d_in[7];
    const float* bn1b     = (const float*)d_in[8];
    const float* bn1m     = (const float*)d_in[9];
    const float* bn1v     = (const float*)d_in[10];
    const float* W2       = (const float*)d_in[11];
    const float* a2s      = (const float*)d_in[12];
    const float* a2d      = (const float*)d_in[13];
    const float* b2       = (const float*)d_in[14];
    const float* bn2g     = (const float*)d_in[15];
    const float* bn2b     = (const float*)d_in[16];
    const float* bn2m     = (const float*)d_in[17];
    const float* bn2v     = (const float*)d_in[18];
    const float* W3       = (const float*)d_in[19];
    const float* a3s      = (const float*)d_in[20];
    const float* a3d      = (const float*)d_in[21];
    const float* b3       = (const float*)d_in[22];
    const float* lin1w    = (const float*)d_in[23];
    const float* lin1b    = (const float*)d_in[24];
    const float* lin2w    = (const float*)d_in[25];
    const float* lin2b    = (const float*)d_in[26];
    float* out = (float*)d_out;

    float *hlin, *hagg, *als, *ald, *ee, *denom, *pooled;
    int *counts, *cursor, *rowptr, *csr_src, *csr_eid, *cnt;
    cudaGetSymbolAddress((void**)&hlin,    g_hlin);
    cudaGetSymbolAddress((void**)&hagg,    g_hagg);
    cudaGetSymbolAddress((void**)&als,     g_als);
    cudaGetSymbolAddress((void**)&ald,     g_ald);
    cudaGetSymbolAddress((void**)&ee,      g_ee);
    cudaGetSymbolAddress((void**)&denom,   g_denom);
    cudaGetSymbolAddress((void**)&pooled,  g_pooled);
    cudaGetSymbolAddress((void**)&counts,  g_counts);
    cudaGetSymbolAddress((void**)&cursor,  g_cursor);
    cudaGetSymbolAddress((void**)&rowptr,  g_rowptr);
    cudaGetSymbolAddress((void**)&csr_src, g_csr_src);
    cudaGetSymbolAddress((void**)&csr_eid, g_csr_eid);
    cudaGetSymbolAddress((void**)&cnt,     g_cnt);

    const int TB = 256;
    const int edgeBlocks = cdiv(ETOT, TB);
    const int nodeWarpBlocks = cdiv(NN * 32, TB);

    // ---- CSR build ----
    fill_zero_i<<<cdiv(NN, TB), TB>>>(counts, NN);
    fill_zero_i<<<cdiv(NN, TB), TB>>>(cursor, NN);
    hist_kernel<<<edgeBlocks, TB>>>(ei, counts);
    scan_kernel<<<1, 1024>>>(counts, rowptr);
    scatter_kernel<<<edgeBlocks, TB>>>(ei, rowptr, cursor, csr_src, csr_eid);

    // ---- Layer 1 ----
    {
        dim3 grid(cdiv(HC12, BN), cdiv(NN, BM));
        sgemm_kernel<<<grid, 256>>>(x, W1, hlin, NN, HC12, FIN);
        attn_logits_kernel<HC12, 4><<<nodeWarpBlocks, TB>>>(hlin, a1s, a1d, als, ald);
        fill_zero_f<<<cdiv(NN * 4, TB), TB>>>(denom, NN * 4);
        edge_exp_kernel<4><<<edgeBlocks, TB>>>(ei, als, ald, ee, denom);
        gat_aggregate_kernel<HC12, 4, 0><<<nodeWarpBlocks, TB>>>(
            hlin, rowptr, csr_src, csr_eid, ee, denom, b1, bn1g, bn1b, bn1m, bn1v, hagg);
    }
    // ---- Layer 2 ----
    {
        dim3 grid(cdiv(HC12, BN), cdiv(NN, BM));
        sgemm_kernel<<<grid, 256>>>(hagg, W2, hlin, NN, HC12, HC12);
        attn_logits_kernel<HC12, 4><<<nodeWarpBlocks, TB>>>(hlin, a2s, a2d, als, ald);
        fill_zero_f<<<cdiv(NN * 4, TB), TB>>>(denom, NN * 4);
        edge_exp_kernel<4><<<edgeBlocks, TB>>>(ei, als, ald, ee, denom);
        gat_aggregate_kernel<HC12, 4, 0><<<nodeWarpBlocks, TB>>>(
            hlin, rowptr, csr_src, csr_eid, ee, denom, b2, bn2g, bn2b, bn2m, bn2v, hagg);
    }
    // ---- Layer 3 (1 head, 64 channels, no BN) ----
    {
        dim3 grid(cdiv(HC3, BN), cdiv(NN, BM));
        sgemm_kernel<<<grid, 256>>>(hagg, W3, hlin, NN, HC3, HC12);
        attn_logits_kernel<HC3, 1><<<nodeWarpBlocks, TB>>>(hlin, a3s, a3d, als, ald);
        fill_zero_f<<<cdiv(NN, TB), TB>>>(denom, NN);
        edge_exp_kernel<1><<<edgeBlocks, TB>>>(ei, als, ald, ee, denom);
        gat_aggregate_kernel<HC3, 1, 1><<<nodeWarpBlocks, TB>>>(
            hlin, rowptr, csr_src, csr_eid, ee, denom, b3,
            nullptr, nullptr, nullptr, nullptr, hagg);
    }
    // ---- Pool + MLP ----
    fill_zero_f<<<cdiv(NGRAPH * HC3, TB), TB>>>(pooled, NGRAPH * HC3);
    fill_zero_i<<<1, NGRAPH>>>(cnt, NGRAPH);
    pool_kernel<<<nodeWarpBlocks, TB>>>(hagg, batch, pooled, cnt);
    mlp_kernel<<<NGRAPH, HC3>>>(pooled, cnt, lin1w, lin1b, lin2w, lin2b, out);

    (void)in_sizes; (void)n_in; (void)out_size;
}

// round 3
// speedup vs baseline: 1.9137x; 1.9137x over previous
#include <cuda_runtime.h>
#include <cuda_bf16.h>
#include <math.h>

// ---------------- problem constants ----------------
#define NN      20000
#define EDG     320000
#define ETOT    (EDG + NN)      // edges + self loops
#define FIN     512
#define HC12    256             // 4 heads * 64
#define HC3     64
#define NGRAPH  64
#define NCLASS  5
#define SLOPE   0.2f
#define EPS_BN  1e-5f
#define NBLK1   ((NN + 255) / 256)   // 79 scan blocks

// ---------------- device scratch ----------------
__device__ float g_hlin[(size_t)NN * HC12];
__device__ float g_hagg[(size_t)NN * HC12];
__device__ float g_als[NN * 4];
__device__ float g_ald[NN * 4];
__device__ float g_ee[(size_t)ETOT * 4];
__device__ int   g_counts[NN];
__device__ int   g_rowptr[NN + 1];
__device__ int   g_csr_src[ETOT];
__device__ int   g_csr_dst[ETOT];
__device__ int   g_bsums[128];
__device__ float g_pooled[NGRAPH * HC3];
__device__ int   g_cnt[NGRAPH];

static inline int cdiv(int a, int b) { return (a + b - 1) / b; }

// ---------------- small utility kernels ----------------
__global__ void zero_counts(int* p) {
    int i = blockIdx.x * blockDim.x + threadIdx.x;
    if (i < NN) p[i] = 0;
}
__global__ void pool_zero(float* pooled, int* cnt) {
    int i = blockIdx.x * blockDim.x + threadIdx.x;
    if (i < NGRAPH * HC3) pooled[i] = 0.0f;
    if (i < NGRAPH) cnt[i] = 0;
}

// ---------------- CSR build ----------------
__global__ void hist_kernel(const int* __restrict__ ei, int* __restrict__ counts) {
    int e = blockIdx.x * blockDim.x + threadIdx.x;
    if (e >= ETOT) return;
    int d = (e < EDG) ? ei[EDG + e] : (e - EDG);
    atomicAdd(&counts[d], 1);
}

// 3-pass parallel exclusive scan: counts -> rowptr
__global__ void scan_pass1(const int* __restrict__ counts, int* __restrict__ rowptr,
                           int* __restrict__ bsums) {
    __shared__ int wsum[8];
    int b = blockIdx.x, t = threadIdx.x;
    int i = b * 256 + t;
    int x = (i < NN) ? counts[i] : 0;
#pragma unroll
    for (int o = 1; o < 32; o <<= 1) {
        int y = __shfl_up_sync(0xffffffffu, x, o);
        if ((t & 31) >= o) x += y;
    }
    if ((t & 31) == 31) wsum[t >> 5] = x;
    __syncthreads();
    if (t < 8) {
        int y = wsum[t];
#pragma unroll
        for (int o = 1; o < 8; o <<= 1) {
            int z = __shfl_up_sync(0xffu, y, o);
            if (t >= o) y += z;
        }
        wsum[t] = y;
    }
    __syncthreads();
    int off = (t >= 32) ? wsum[(t >> 5) - 1] : 0;
    int incl = x + off;
    if (i < NN) rowptr[i + 1] = incl;
    if (t == 255) bsums[b] = incl;
}
__global__ void scan_pass2(int* bsums) {
    __shared__ int wsum[4];
    int t = threadIdx.x;  // 128 threads
    int x = (t < NBLK1) ? bsums[t] : 0;
#pragma unroll
    for (int o = 1; o < 32; o <<= 1) {
        int y = __shfl_up_sync(0xffffffffu, x, o);
        if ((t & 31) >= o) x += y;
    }
    if ((t & 31) == 31) wsum[t >> 5] = x;
    __syncthreads();
    if (t < 4) {
        int y = wsum[t];
#pragma unroll
        for (int o = 1; o < 4; o <<= 1) {
            int z = __shfl_up_sync(0xfu, y, o);
            if (t >= o) y += z;
        }
        wsum[t] = y;
    }
    __syncthreads();
    int off = (t >= 32) ? wsum[(t >> 5) - 1] : 0;
    if (t < NBLK1) bsums[t] = x + off;
}
__global__ void scan_pass3(int* __restrict__ rowptr, const int* __restrict__ bsums) {
    int b = blockIdx.x, t = threadIdx.x;
    if (b == 0) { if (t == 0) rowptr[0] = 0; return; }
    int i = b * 256 + t;
    int off = bsums[b - 1];
    if (i < NN) rowptr[i + 1] += off;
}

// scatter; reuses counts[] as cursor via atomicSub
__global__ void scatter_kernel(const int* __restrict__ ei,
                               const int* __restrict__ rowptr,
                               int* __restrict__ counts,
                               int* __restrict__ csr_src,
                               int* __restrict__ csr_dst) {
    int e = blockIdx.x * blockDim.x + threadIdx.x;
    if (e >= ETOT) return;
    int s, d;
    if (e < EDG) { s = ei[e]; d = ei[EDG + e]; }
    else         { s = d = e - EDG; }
    int pos = rowptr[d] + atomicSub(&counts[d], 1) - 1;
    csr_src[pos] = s;
    csr_dst[pos] = d;
}

// ---------------- tf32 tensor-core GEMM ----------------
__device__ __forceinline__ unsigned f2tf(float x) {
    unsigned u;
    asm("cvt.rna.tf32.f32 %0, %1;" : "=r"(u) : "f"(x));
    return u;
}
__device__ __forceinline__ void mma_tf32(float* d, const unsigned* a, const unsigned* b) {
    asm volatile(
        "mma.sync.aligned.m16n8k8.row.col.f32.tf32.tf32.f32 "
        "{%0,%1,%2,%3}, {%4,%5,%6,%7}, {%8,%9}, {%0,%1,%2,%3};\n"
        : "+f"(d[0]), "+f"(d[1]), "+f"(d[2]), "+f"(d[3])
        : "r"(a[0]), "r"(a[1]), "r"(a[2]), "r"(a[3]), "r"(b[0]), "r"(b[1]));
}

// C[M,N] = A[M,K] * B[K,N], row-major, BM=128, BK=16, 256 threads (8 warps)
template <int BN, int WRM, int WRN>
__global__ __launch_bounds__(256) void tf32_gemm(const float* __restrict__ A,
                                                 const float* __restrict__ B,
                                                 float* __restrict__ C,
                                                 int M, int N, int K) {
    constexpr int BM = 128, BK = 16;
    constexpr int WM = BM / WRM, WN = BN / WRN;
    constexpr int MT = WM / 16, NT = WN / 8;
    constexpr int AS = BK + 4;     // padded A smem row stride (floats)
    constexpr int BS = BN + 8;     // padded B smem row stride
    constexpr int NB4 = BN / 4;
    constexpr int BLD = (BN * BK) / (4 * 256) > 0 ? (BN * BK) / (4 * 256) : 1;

    __shared__ unsigned As[2][BM * AS];
    __shared__ unsigned Bs[2][BK * BS];

    int tid = threadIdx.x, lane = tid & 31, wid = tid >> 5;
    int by = blockIdx.y * BM, bx = blockIdx.x * BN;
    int wm = (wid / WRN) * WM, wn = (wid % WRN) * WN;

    float acc[MT][NT][4];
#pragma unroll
    for (int i = 0; i < MT; i++)
#pragma unroll
        for (int j = 0; j < NT; j++)
#pragma unroll
            for (int r = 0; r < 4; r++) acc[i][j][r] = 0.0f;

    float4 aF[2], bF[BLD];
    const int ntiles = K / BK;

    // fetch tile kt into registers
    auto fetch = [&](int kt) {
        int k0 = kt * BK;
#pragma unroll
        for (int j = 0; j < 2; j++) {
            int i = tid + j * 256;
            int row = i >> 2, c4 = i & 3;
            int gr = by + row;
            if (gr < M)
                aF[j] = *reinterpret_cast<const float4*>(A + (size_t)gr * K + k0 + c4 * 4);
            else
                aF[j] = make_float4(0.f, 0.f, 0.f, 0.f);
        }
#pragma unroll
        for (int j = 0; j < BLD; j++) {
            int i = tid + j * 256;
            if (i < BK * NB4) {
                int row = i / NB4, c4 = i % NB4;
                bF[j] = *reinterpret_cast<const float4*>(B + (size_t)(k0 + row) * N + bx + c4 * 4);
            }
        }
    };
    auto store = [&](int buf) {
#pragma unroll
        for (int j = 0; j < 2; j++) {
            int i = tid + j * 256;
            int row = i >> 2, c4 = i & 3;
            uint4 u;
            u.x = f2tf(aF[j].x); u.y = f2tf(aF[j].y); u.z = f2tf(aF[j].z); u.w = f2tf(aF[j].w);
            *reinterpret_cast<uint4*>(&As[buf][row * AS + c4 * 4]) = u;
        }
#pragma unroll
        for (int j = 0; j < BLD; j++) {
            int i = tid + j * 256;
            if (i < BK * NB4) {
                int row = i / NB4, c4 = i % NB4;
                uint4 u;
                u.x = f2tf(bF[j].x); u.y = f2tf(bF[j].y); u.z = f2tf(bF[j].z); u.w = f2tf(bF[j].w);
                *reinterpret_cast<uint4*>(&Bs[buf][row * BS + c4 * 4]) = u;
            }
        }
    };
    auto compute = [&](int buf) {
#pragma unroll
        for (int ks = 0; ks < BK; ks += 8) {
            unsigned af[MT][4], bf[NT][2];
#pragma unroll
            for (int mt = 0; mt < MT; mt++) {
                int r0 = wm + mt * 16 + (lane >> 2);
                int c0 = ks + (lane & 3);
                af[mt][0] = As[buf][r0 * AS + c0];
                af[mt][1] = As[buf][(r0 + 8) * AS + c0];
                af[mt][2] = As[buf][r0 * AS + c0 + 4];
                af[mt][3] = As[buf][(r0 + 8) * AS + c0 + 4];
            }
#pragma unroll
            for (int nt = 0; nt < NT; nt++) {
                int kk = ks + (lane & 3);
                int n0 = wn + nt * 8 + (lane >> 2);
                bf[nt][0] = Bs[buf][kk * BS + n0];
                bf[nt][1] = Bs[buf][(kk + 4) * BS + n0];
            }
#pragma unroll
            for (int mt = 0; mt < MT; mt++)
#pragma unroll
                for (int nt = 0; nt < NT; nt++)
                    mma_tf32(acc[mt][nt], af[mt], bf[nt]);
        }
    };

    fetch(0);
    store(0);
    __syncthreads();
    for (int kt = 0; kt < ntiles; kt++) {
        int cur = kt & 1;
        if (kt + 1 < ntiles) fetch(kt + 1);
        compute(cur);
        if (kt + 1 < ntiles) store(cur ^ 1);
        __syncthreads();
    }

#pragma unroll
    for (int mt = 0; mt < MT; mt++) {
#pragma unroll
        for (int nt = 0; nt < NT; nt++) {
            int r0 = by + wm + mt * 16 + (lane >> 2);
            int c0 = bx + wn + nt * 8 + 2 * (lane & 3);
            if (r0 < M) {
                float2 v = make_float2(acc[mt][nt][0], acc[mt][nt][1]);
                *reinterpret_cast<float2*>(&C[(size_t)r0 * N + c0]) = v;
            }
            if (r0 + 8 < M) {
                float2 v = make_float2(acc[mt][nt][2], acc[mt][nt][3]);
                *reinterpret_cast<float2*>(&C[(size_t)(r0 + 8) * N + c0]) = v;
            }
        }
    }
}

// ---------------- attention logits: warp per node ----------------
template <int HCv, int Hv>
__global__ void attn_logits_kernel(const float* __restrict__ h,
                                   const float* __restrict__ a_s,
                                   const float* __restrict__ a_d,
                                   float* __restrict__ al_s,
                                   float* __restrict__ al_d) {
    int gw = (blockIdx.x * blockDim.x + threadIdx.x) >> 5;
    int lane = threadIdx.x & 31;
    if (gw >= NN) return;
    const int J = HCv / 32;
    float as_acc[Hv], ad_acc[Hv];
#pragma unroll
    for (int hh = 0; hh < Hv; hh++) { as_acc[hh] = 0.f; ad_acc[hh] = 0.f; }
    const float* hp = h + (size_t)gw * HCv;
#pragma unroll
    for (int j = 0; j < J; j++) {
        int c = lane + 32 * j;
        float v = hp[c];
        int hh = c >> 6;
        as_acc[hh] += v * a_s[c];
        ad_acc[hh] += v * a_d[c];
    }
#pragma unroll
    for (int hh = 0; hh < Hv; hh++) {
        float s = as_acc[hh], d = ad_acc[hh];
#pragma unroll
        for (int off = 16; off; off >>= 1) {
            s += __shfl_down_sync(0xffffffffu, s, off);
            d += __shfl_down_sync(0xffffffffu, d, off);
        }
        if (lane == 0) {
            al_s[gw * Hv + hh] = s;
            al_d[gw * Hv + hh] = d;
        }
    }
}

// ---------------- edge weights in CSR order ----------------
template <int Hv>
__global__ void edge_exp_kernel(const int* __restrict__ csr_src,
                                const int* __restrict__ csr_dst,
                                const float* __restrict__ al_s,
                                const float* __restrict__ al_d,
                                float* __restrict__ ee) {
    int p = blockIdx.x * blockDim.x + threadIdx.x;
    if (p >= ETOT) return;
    int s = csr_src[p], d = csr_dst[p];
#pragma unroll
    for (int hh = 0; hh < Hv; hh++) {
        float v = al_s[s * Hv + hh] + al_d[d * Hv + hh];
        v = (v > 0.f) ? v : SLOPE * v;
        ee[(size_t)p * Hv + hh] = __expf(v);
    }
}

// ---------------- aggregation (warp per dst), denom computed in-pass ----------------
template <int HCv, int Hv, int MODE>
__global__ void gat_aggregate_kernel(const float* __restrict__ hlin,
                                     const int* __restrict__ rowptr,
                                     const int* __restrict__ csr_src,
                                     const float* __restrict__ ee,
                                     const float* __restrict__ bias,
                                     const float* __restrict__ gamma,
                                     const float* __restrict__ beta,
                                     const float* __restrict__ mean,
                                     const float* __restrict__ var,
                                     float* __restrict__ out) {
    int gw = (blockIdx.x * blockDim.x + threadIdx.x) >> 5;
    int lane = threadIdx.x & 31;
    if (gw >= NN) return;
    const int CPL = HCv / 32;
    int head = (lane * CPL) >> 6;
    float acc[CPL];
#pragma unroll
    for (int j = 0; j < CPL; j++) acc[j] = 0.f;
    float wsum = 0.f;

    int beg = rowptr[gw], end = rowptr[gw + 1];
    int p = beg;
    for (; p + 2 <= end; p += 2) {
        int s0 = __ldg(&csr_src[p]);
        int s1 = __ldg(&csr_src[p + 1]);
        float w0 = __ldg(&ee[(size_t)p * Hv + head]);
        float w1 = __ldg(&ee[(size_t)(p + 1) * Hv + head]);
        wsum += w0 + w1;
        if (CPL == 8) {
            const float4* h0 = reinterpret_cast<const float4*>(hlin + (size_t)s0 * HCv + lane * 8);
            const float4* h1 = reinterpret_cast<const float4*>(hlin + (size_t)s1 * HCv + lane * 8);
            float4 a0 = h0[0], a1 = h0[1], c0 = h1[0], c1 = h1[1];
            acc[0] += w0 * a0.x + w1 * c0.x; acc[1] += w0 * a0.y + w1 * c0.y;
            acc[2] += w0 * a0.z + w1 * c0.z; acc[3] += w0 * a0.w + w1 * c0.w;
            acc[4] += w0 * a1.x + w1 * c1.x; acc[5] += w0 * a1.y + w1 * c1.y;
            acc[6] += w0 * a1.z + w1 * c1.z; acc[7] += w0 * a1.w + w1 * c1.w;
        } else {
            const float2* h0 = reinterpret_cast<const float2*>(hlin + (size_t)s0 * HCv + lane * 2);
            const float2* h1 = reinterpret_cast<const float2*>(hlin + (size_t)s1 * HCv + lane * 2);
            float2 a = h0[0], b = h1[0];
            acc[0] += w0 * a.x + w1 * b.x;
            acc[1] += w0 * a.y + w1 * b.y;
        }
    }
    if (p < end) {
        int s0 = __ldg(&csr_src[p]);
        float w0 = __ldg(&ee[(size_t)p * Hv + head]);
        wsum += w0;
        if (CPL == 8) {
            const float4* h0 = reinterpret_cast<const float4*>(hlin + (size_t)s0 * HCv + lane * 8);
            float4 a0 = h0[0], a1 = h0[1];
            acc[0] += w0 * a0.x; acc[1] += w0 * a0.y; acc[2] += w0 * a0.z; acc[3] += w0 * a0.w;
            acc[4] += w0 * a1.x; acc[5] += w0 * a1.y; acc[6] += w0 * a1.z; acc[7] += w0 * a1.w;
        } else {
            const float2* h0 = reinterpret_cast<const float2*>(hlin + (size_t)s0 * HCv + lane * 2);
            float2 a = h0[0];
            acc[0] += w0 * a.x;
            acc[1] += w0 * a.y;
        }
    }

    float inv = 1.0f / (wsum + 1e-16f);
#pragma unroll
    for (int j = 0; j < CPL; j++) {
        int c = lane * CPL + j;
        float v = acc[j] * inv + bias[c];
        if (MODE == 0) {
            v = (v - mean[c]) * rsqrtf(var[c] + EPS_BN) * gamma[c] + beta[c];
        }
        v = (v > 0.f) ? v : 0.f;
        out[(size_t)gw * HCv + c] = v;
    }
}

// ---------------- mean pool (warp per node) ----------------
__global__ void pool_kernel(const float* __restrict__ h, const int* __restrict__ batch,
                            float* __restrict__ pooled, int* __restrict__ cnt) {
    int gw = (blockIdx.x * blockDim.x + threadIdx.x) >> 5;
    int lane = threadIdx.x & 31;
    if (gw >= NN) return;
    int b = batch[gw];
#pragma unroll
    for (int j = 0; j < 2; j++) {
        int c = lane + 32 * j;
        atomicAdd(&pooled[b * HC3 + c], h[(size_t)gw * HC3 + c]);
    }
    if (lane == 0) atomicAdd(&cnt[b], 1);
}

// ---------------- final MLP ----------------
__global__ void mlp_kernel(const float* __restrict__ pooled, const int* __restrict__ cnt,
                           const float* __restrict__ w1, const float* __restrict__ b1,
                           const float* __restrict__ w2, const float* __restrict__ b2,
                           float* __restrict__ out) {
    int g = blockIdx.x;
    int t = threadIdx.x;
    __shared__ float m[HC3];
    __shared__ float hid[32];
    float c = (float)cnt[g];
    if (c < 1.0f) c = 1.0f;
    m[t] = pooled[g * HC3 + t] / c;
    __syncthreads();
    if (t < 32) {
        float s = b1[t];
#pragma unroll
        for (int k = 0; k < HC3; k++) s += m[k] * w1[k * 32 + t];
        hid[t] = (s > 0.f) ? s : 0.f;
    }
    __syncthreads();
    if (t < NCLASS) {
        float s = b2[t];
#pragma unroll
        for (int k = 0; k < 32; k++) s += hid[k] * w2[k * NCLASS + t];
        out[g * NCLASS + t] = s;
    }
}

// ---------------- host orchestration ----------------
extern "C" void kernel_launch(void* const* d_in, const int* in_sizes, int n_in,
                              void* d_out, int out_size) {
    const float* x     = (const float*)d_in[0];
    const int*   ei    = (const int*)  d_in[1];
    const int*   batch = (const int*)  d_in[2];
    const float* W1    = (const float*)d_in[3];
    const float* a1s   = (const float*)d_in[4];
    const float* a1d   = (const float*)d_in[5];
    const float* b1    = (const float*)d_in[6];
    const float* bn1g  = (const float*)d_in[7];
    const float* bn1b  = (const float*)d_in[8];
    const float* bn1m  = (const float*)d_in[9];
    const float* bn1v  = (const float*)d_in[10];
    const float* W2    = (const float*)d_in[11];
    const float* a2s   = (const float*)d_in[12];
    const float* a2d   = (const float*)d_in[13];
    const float* b2    = (const float*)d_in[14];
    const float* bn2g  = (const float*)d_in[15];
    const float* bn2b  = (const float*)d_in[16];
    const float* bn2m  = (const float*)d_in[17];
    const float* bn2v  = (const float*)d_in[18];
    const float* W3    = (const float*)d_in[19];
    const float* a3s   = (const float*)d_in[20];
    const float* a3d   = (const float*)d_in[21];
    const float* b3    = (const float*)d_in[22];
    const float* lin1w = (const float*)d_in[23];
    const float* lin1b = (const float*)d_in[24];
    const float* lin2w = (const float*)d_in[25];
    const float* lin2b = (const float*)d_in[26];
    float* out = (float*)d_out;

    float *hlin, *hagg, *als, *ald, *ee, *pooled;
    int *counts, *rowptr, *csr_src, *csr_dst, *bsums, *cnt;
    cudaGetSymbolAddress((void**)&hlin,    g_hlin);
    cudaGetSymbolAddress((void**)&hagg,    g_hagg);
    cudaGetSymbolAddress((void**)&als,     g_als);
    cudaGetSymbolAddress((void**)&ald,     g_ald);
    cudaGetSymbolAddress((void**)&ee,      g_ee);
    cudaGetSymbolAddress((void**)&pooled,  g_pooled);
    cudaGetSymbolAddress((void**)&counts,  g_counts);
    cudaGetSymbolAddress((void**)&rowptr,  g_rowptr);
    cudaGetSymbolAddress((void**)&csr_src, g_csr_src);
    cudaGetSymbolAddress((void**)&csr_dst, g_csr_dst);
    cudaGetSymbolAddress((void**)&bsums,   g_bsums);
    cudaGetSymbolAddress((void**)&cnt,     g_cnt);

    const int TB = 256;
    const int edgeBlocks = cdiv(ETOT, TB);
    const int nodeWarpBlocks = cdiv(NN * 32, TB);

    // ---- CSR build ----
    zero_counts<<<cdiv(NN, TB), TB>>>(counts);
    hist_kernel<<<edgeBlocks, TB>>>(ei, counts);
    scan_pass1<<<NBLK1, 256>>>(counts, rowptr, bsums);
    scan_pass2<<<1, 128>>>(bsums);
    scan_pass3<<<NBLK1, 256>>>(rowptr, bsums);
    scatter_kernel<<<edgeBlocks, TB>>>(ei, rowptr, counts, csr_src, csr_dst);

    // ---- Layer 1 ----
    {
        dim3 grid(HC12 / 128, cdiv(NN, 128));
        tf32_gemm<128, 2, 4><<<grid, 256>>>(x, W1, hlin, NN, HC12, FIN);
        attn_logits_kernel<HC12, 4><<<nodeWarpBlocks, TB>>>(hlin, a1s, a1d, als, ald);
        edge_exp_kernel<4><<<edgeBlocks, TB>>>(csr_src, csr_dst, als, ald, ee);
        gat_aggregate_kernel<HC12, 4, 0><<<nodeWarpBlocks, TB>>>(
            hlin, rowptr, csr_src, ee, b1, bn1g, bn1b, bn1m, bn1v, hagg);
    }
    // ---- Layer 2 ----
    {
        dim3 grid(HC12 / 128, cdiv(NN, 128));
        tf32_gemm<128, 2, 4><<<grid, 256>>>(hagg, W2, hlin, NN, HC12, HC12);
        attn_logits_kernel<HC12, 4><<<nodeWarpBlocks, TB>>>(hlin, a2s, a2d, als, ald);
        edge_exp_kernel<4><<<edgeBlocks, TB>>>(csr_src, csr_dst, als, ald, ee);
        gat_aggregate_kernel<HC12, 4, 0><<<nodeWarpBlocks, TB>>>(
            hlin, rowptr, csr_src, ee, b2, bn2g, bn2b, bn2m, bn2v, hagg);
    }
    // ---- Layer 3 ----
    {
        dim3 grid(HC3 / 64, cdiv(NN, 128));
        tf32_gemm<64, 4, 2><<<grid, 256>>>(hagg, W3, hlin, NN, HC3, HC12);
        attn_logits_kernel<HC3, 1><<<nodeWarpBlocks, TB>>>(hlin, a3s, a3d, als, ald);
        edge_exp_kernel<1><<<edgeBlocks, TB>>>(csr_src, csr_dst, als, ald, ee);
        gat_aggregate_kernel<HC3, 1, 1><<<nodeWarpBlocks, TB>>>(
            hlin, rowptr, csr_src, ee, b3, nullptr, nullptr, nullptr, nullptr, hagg);
    }
    // ---- Pool + MLP ----
    pool_zero<<<cdiv(NGRAPH * HC3, TB), TB>>>(pooled, cnt);
    pool_kernel<<<nodeWarpBlocks, TB>>>(hagg, batch, pooled, cnt);
    mlp_kernel<<<NGRAPH, HC3>>>(pooled, cnt, lin1w, lin1b, lin2w, lin2b, out);

    (void)in_sizes; (void)n_in; (void)out_size;
}

// round 7
// speedup vs baseline: 2.2187x; 1.1594x over previous
#include <cuda_runtime.h>
#include <cuda_bf16.h>
#include <cstdint>
#include <math.h>

// ---------------- problem constants ----------------
#define NN      20000
#define EDG     320000
#define ETOT    (EDG + NN)
#define FIN     512
#define HC12    256
#define HC3     64
#define NGRAPH  64
#define NCLASS  5
#define SLOPE   0.2f
#define EPS_BN  1e-5f
#define NBLK1   ((NN + 255) / 256)

// ---------------- device scratch ----------------
__device__ float g_hlin[(size_t)NN * HC12];
__device__ float g_hagg[(size_t)NN * HC12];
__device__ float g_als[NN * 4];
__device__ float g_ald[NN * 4];
__device__ int   g_counts[NN];
__device__ int   g_rowptr[NN + 1];
__device__ int   g_csr_src[ETOT];
__device__ int   g_bsums[128];
__device__ float g_pooled[NGRAPH * HC3];
__device__ int   g_cnt[NGRAPH];

static inline int cdiv(int a, int b) { return (a + b - 1) / b; }

// ---------------- small utility kernels ----------------
__global__ void zero_counts(int* p) {
    int i = blockIdx.x * blockDim.x + threadIdx.x;
    if (i < NN) p[i] = 0;
}
__global__ void pool_zero(float* pooled, int* cnt) {
    int i = blockIdx.x * blockDim.x + threadIdx.x;
    if (i < NGRAPH * HC3) pooled[i] = 0.0f;
    if (i < NGRAPH) cnt[i] = 0;
}

// ---------------- CSR build ----------------
__global__ void hist_kernel(const int* __restrict__ ei, int* __restrict__ counts) {
    int e = blockIdx.x * blockDim.x + threadIdx.x;
    if (e >= ETOT) return;
    int d = (e < EDG) ? ei[EDG + e] : (e - EDG);
    atomicAdd(&counts[d], 1);
}

__global__ void scan_pass1(const int* __restrict__ counts, int* __restrict__ rowptr,
                           int* __restrict__ bsums) {
    __shared__ int wsum[8];
    int b = blockIdx.x, t = threadIdx.x;
    int i = b * 256 + t;
    int x = (i < NN) ? counts[i] : 0;
#pragma unroll
    for (int o = 1; o < 32; o <<= 1) {
        int y = __shfl_up_sync(0xffffffffu, x, o);
        if ((t & 31) >= o) x += y;
    }
    if ((t & 31) == 31) wsum[t >> 5] = x;
    __syncthreads();
    if (t < 8) {
        int y = wsum[t];
#pragma unroll
        for (int o = 1; o < 8; o <<= 1) {
            int z = __shfl_up_sync(0xffu, y, o);
            if (t >= o) y += z;
        }
        wsum[t] = y;
    }
    __syncthreads();
    int off = (t >= 32) ? wsum[(t >> 5) - 1] : 0;
    int incl = x + off;
    if (i < NN) rowptr[i + 1] = incl;
    if (t == 255) bsums[b] = incl;
}
__global__ void scan_pass2(int* bsums) {
    __shared__ int wsum[4];
    int t = threadIdx.x;
    int x = (t < NBLK1) ? bsums[t] : 0;
#pragma unroll
    for (int o = 1; o < 32; o <<= 1) {
        int y = __shfl_up_sync(0xffffffffu, x, o);
        if ((t & 31) >= o) x += y;
    }
    if ((t & 31) == 31) wsum[t >> 5] = x;
    __syncthreads();
    if (t < 4) {
        int y = wsum[t];
#pragma unroll
        for (int o = 1; o < 4; o <<= 1) {
            int z = __shfl_up_sync(0xfu, y, o);
            if (t >= o) y += z;
        }
        wsum[t] = y;
    }
    __syncthreads();
    int off = (t >= 32) ? wsum[(t >> 5) - 1] : 0;
    if (t < NBLK1) bsums[t] = x + off;
}
__global__ void scan_pass3(int* __restrict__ rowptr, const int* __restrict__ bsums) {
    int b = blockIdx.x, t = threadIdx.x;
    if (b == 0) { if (t == 0) rowptr[0] = 0; return; }
    int i = b * 256 + t;
    int off = bsums[b - 1];
    if (i < NN) rowptr[i + 1] += off;
}

__global__ void scatter_kernel(const int* __restrict__ ei,
                               const int* __restrict__ rowptr,
                               int* __restrict__ counts,
                               int* __restrict__ csr_src) {
    int e = blockIdx.x * blockDim.x + threadIdx.x;
    if (e >= ETOT) return;
    int s, d;
    if (e < EDG) { s = ei[e]; d = ei[EDG + e]; }
    else         { s = d = e - EDG; }
    int pos = rowptr[d] + atomicSub(&counts[d], 1) - 1;
    csr_src[pos] = s;
}

// ---------------- cp.async helpers ----------------
__device__ __forceinline__ void cpa16(unsigned int dst, const void* src) {
    asm volatile("cp.async.cg.shared.global [%0], [%1], 16;\n" :: "r"(dst), "l"(src));
}
__device__ __forceinline__ void cp_commit() { asm volatile("cp.async.commit_group;\n"); }
template <int Ngrp>
__device__ __forceinline__ void cp_wait() { asm volatile("cp.async.wait_group %0;\n" :: "n"(Ngrp)); }

// round-to-nearest tf32 conversion (unbiased) — applied on smem->fragment path
__device__ __forceinline__ unsigned f2tf(float x) {
    unsigned u;
    asm("cvt.rna.tf32.f32 %0, %1;" : "=r"(u) : "f"(x));
    return u;
}

__device__ __forceinline__ void mma_tf32(float* d, const unsigned* a, const unsigned* b) {
    asm volatile(
        "mma.sync.aligned.m16n8k8.row.col.f32.tf32.tf32.f32 "
        "{%0,%1,%2,%3}, {%4,%5,%6,%7}, {%8,%9}, {%0,%1,%2,%3};\n"
        : "+f"(d[0]), "+f"(d[1]), "+f"(d[2]), "+f"(d[3])
        : "r"(a[0]), "r"(a[1]), "r"(a[2]), "r"(a[3]), "r"(b[0]), "r"(b[1]));
}

// ---------------- tf32 GEMM + fused attention-logit epilogue ----------------
template <int BN, int WRM, int WRN, int Hv>
__global__ __launch_bounds__(256) void gemm_attn(const float* __restrict__ A,
                                                 const float* __restrict__ B,
                                                 float* __restrict__ C,
                                                 const float* __restrict__ a_s,
                                                 const float* __restrict__ a_d,
                                                 float* __restrict__ al_s,
                                                 float* __restrict__ al_d,
                                                 int M, int N, int K) {
    constexpr int BM = 128, BK = 16;
    constexpr int WM = BM / WRM, WN = BN / WRN;
    constexpr int MT = WM / 16, NT = WN / 8;
    constexpr int AS = BK + 4;
    constexpr int BS = BN + 8;
    constexpr int NB4 = BN / 4;
    constexpr int BLDB = (BK * NB4 + 255) / 256;
    constexpr int HB = BN / 64;

    __shared__ float As[2][BM * AS];
    __shared__ float Bs[2][BK * BS];
    __shared__ float sS[BM * HB];
    __shared__ float sD[BM * HB];

    int tid = threadIdx.x, lane = tid & 31, wid = tid >> 5;
    int by = blockIdx.y * BM, bx = blockIdx.x * BN;
    int wm = (wid / WRN) * WM, wn = (wid % WRN) * WN;

    float acc[MT][NT][4];
#pragma unroll
    for (int i = 0; i < MT; i++)
#pragma unroll
        for (int j = 0; j < NT; j++)
#pragma unroll
            for (int r = 0; r < 4; r++) acc[i][j][r] = 0.0f;

    const int ntiles = K / BK;

    auto fetch = [&](int kt, int buf) {
        int k0 = kt * BK;
#pragma unroll
        for (int j = 0; j < 2; j++) {
            int i = tid + j * 256;
            int row = i >> 2, c4 = i & 3;
            int gr = by + row; if (gr >= M) gr = M - 1;
            unsigned int dst = (unsigned int)__cvta_generic_to_shared(&As[buf][row * AS + c4 * 4]);
            cpa16(dst, A + (size_t)gr * K + k0 + c4 * 4);
        }
#pragma unroll
        for (int j = 0; j < BLDB; j++) {
            int i = tid + j * 256;
            if (i < BK * NB4) {
                int row = i / NB4, c4 = i % NB4;
                unsigned int dst = (unsigned int)__cvta_generic_to_shared(&Bs[buf][row * BS + c4 * 4]);
                cpa16(dst, B + (size_t)(k0 + row) * N + bx + c4 * 4);
            }
        }
    };
    auto compute = [&](int buf) {
#pragma unroll
        for (int ks = 0; ks < BK; ks += 8) {
            unsigned af[MT][4], bf[NT][2];
#pragma unroll
            for (int mt = 0; mt < MT; mt++) {
                int r0 = wm + mt * 16 + (lane >> 2);
                int c0 = ks + (lane & 3);
                af[mt][0] = f2tf(As[buf][r0 * AS + c0]);
                af[mt][1] = f2tf(As[buf][(r0 + 8) * AS + c0]);
                af[mt][2] = f2tf(As[buf][r0 * AS + c0 + 4]);
                af[mt][3] = f2tf(As[buf][(r0 + 8) * AS + c0 + 4]);
            }
#pragma unroll
            for (int nt = 0; nt < NT; nt++) {
                int kk = ks + (lane & 3);
                int n0 = wn + nt * 8 + (lane >> 2);
                bf[nt][0] = f2tf(Bs[buf][kk * BS + n0]);
                bf[nt][1] = f2tf(Bs[buf][(kk + 4) * BS + n0]);
            }
#pragma unroll
            for (int mt = 0; mt < MT; mt++)
#pragma unroll
                for (int nt = 0; nt < NT; nt++)
                    mma_tf32(acc[mt][nt], af[mt], bf[nt]);
        }
    };

    fetch(0, 0);
    cp_commit();
    for (int kt = 0; kt < ntiles; kt++) {
        int buf = kt & 1;
        if (kt + 1 < ntiles) { fetch(kt + 1, buf ^ 1); cp_commit(); cp_wait<1>(); }
        else                 { cp_wait<0>(); }
        __syncthreads();
        compute(buf);
        __syncthreads();
    }

    // ---- store C ----
#pragma unroll
    for (int mt = 0; mt < MT; mt++) {
#pragma unroll
        for (int nt = 0; nt < NT; nt++) {
            int r0 = by + wm + mt * 16 + (lane >> 2);
            int c0 = bx + wn + nt * 8 + 2 * (lane & 3);
            if (r0 < M)
                *reinterpret_cast<float2*>(&C[(size_t)r0 * N + c0]) =
                    make_float2(acc[mt][nt][0], acc[mt][nt][1]);
            if (r0 + 8 < M)
                *reinterpret_cast<float2*>(&C[(size_t)(r0 + 8) * N + c0]) =
                    make_float2(acc[mt][nt][2], acc[mt][nt][3]);
        }
    }

    // ---- fused attention-logit epilogue ----
    for (int i = tid; i < BM * HB; i += 256) { sS[i] = 0.f; sD[i] = 0.f; }
    __syncthreads();

    float as0[NT], as1[NT], ad0[NT], ad1[NT];
#pragma unroll
    for (int nt = 0; nt < NT; nt++) {
        int c = bx + wn + nt * 8 + 2 * (lane & 3);
        as0[nt] = a_s[c]; as1[nt] = a_s[c + 1];
        ad0[nt] = a_d[c]; ad1[nt] = a_d[c + 1];
    }
    int hl = wn >> 6;
#pragma unroll
    for (int mt = 0; mt < MT; mt++) {
        float pslo = 0.f, pshi = 0.f, pdlo = 0.f, pdhi = 0.f;
#pragma unroll
        for (int nt = 0; nt < NT; nt++) {
            pslo += acc[mt][nt][0] * as0[nt] + acc[mt][nt][1] * as1[nt];
            pshi += acc[mt][nt][2] * as0[nt] + acc[mt][nt][3] * as1[nt];
            pdlo += acc[mt][nt][0] * ad0[nt] + acc[mt][nt][1] * ad1[nt];
            pdhi += acc[mt][nt][2] * ad0[nt] + acc[mt][nt][3] * ad1[nt];
        }
        pslo += __shfl_xor_sync(0xffffffffu, pslo, 1);
        pslo += __shfl_xor_sync(0xffffffffu, pslo, 2);
        pshi += __shfl_xor_sync(0xffffffffu, pshi, 1);
        pshi += __shfl_xor_sync(0xffffffffu, pshi, 2);
        pdlo += __shfl_xor_sync(0xffffffffu, pdlo, 1);
        pdlo += __shfl_xor_sync(0xffffffffu, pdlo, 2);
        pdhi += __shfl_xor_sync(0xffffffffu, pdhi, 1);
        pdhi += __shfl_xor_sync(0xffffffffu, pdhi, 2);
        if ((lane & 3) == 0) {
            int r = wm + mt * 16 + (lane >> 2);
            atomicAdd(&sS[r * HB + hl], pslo);
            atomicAdd(&sS[(r + 8) * HB + hl], pshi);
            atomicAdd(&sD[r * HB + hl], pdlo);
            atomicAdd(&sD[(r + 8) * HB + hl], pdhi);
        }
    }
    __syncthreads();
    int headbase = bx >> 6;
    for (int i = tid; i < BM * HB; i += 256) {
        int row = i / HB, h2 = i % HB;
        int gr = by + row;
        if (gr < M) {
            al_s[gr * Hv + headbase + h2] = sS[i];
            al_d[gr * Hv + headbase + h2] = sD[i];
        }
    }
}

// ---------------- aggregation (warp per dst) with inline edge softmax ----------------
template <int HCv, int Hv, int MODE>
__global__ void gat_aggregate_kernel(const float* __restrict__ hlin,
                                     const int* __restrict__ rowptr,
                                     const int* __restrict__ csr_src,
                                     const float* __restrict__ al_s,
                                     const float* __restrict__ al_d,
                                     const float* __restrict__ bias,
                                     const float* __restrict__ gamma,
                                     const float* __restrict__ beta,
                                     const float* __restrict__ mean,
                                     const float* __restrict__ var,
                                     float* __restrict__ out) {
    int gw = (blockIdx.x * blockDim.x + threadIdx.x) >> 5;
    int lane = threadIdx.x & 31;
    if (gw >= NN) return;
    const int CPL = HCv / 32;
    int head = (lane * CPL) >> 6;
    float acc[CPL];
#pragma unroll
    for (int j = 0; j < CPL; j++) acc[j] = 0.f;
    float wsum = 0.f;
    float ald_h = __ldg(&al_d[gw * Hv + head]);

    int beg = rowptr[gw], end = rowptr[gw + 1];
    int p = beg;
    for (; p + 2 <= end; p += 2) {
        int s0 = __ldg(&csr_src[p]);
        int s1 = __ldg(&csr_src[p + 1]);
        float e0 = __ldg(&al_s[s0 * Hv + head]) + ald_h;
        float e1 = __ldg(&al_s[s1 * Hv + head]) + ald_h;
        e0 = (e0 > 0.f) ? e0 : SLOPE * e0;
        e1 = (e1 > 0.f) ? e1 : SLOPE * e1;
        float w0 = __expf(e0), w1 = __expf(e1);
        wsum += w0 + w1;
        if (CPL == 8) {
            const float4* h0 = reinterpret_cast<const float4*>(hlin + (size_t)s0 * HCv + lane * 8);
            const float4* h1 = reinterpret_cast<const float4*>(hlin + (size_t)s1 * HCv + lane * 8);
            float4 a0 = h0[0], a1 = h0[1], c0 = h1[0], c1 = h1[1];
            acc[0] += w0 * a0.x + w1 * c0.x; acc[1] += w0 * a0.y + w1 * c0.y;
            acc[2] += w0 * a0.z + w1 * c0.z; acc[3] += w0 * a0.w + w1 * c0.w;
            acc[4] += w0 * a1.x + w1 * c1.x; acc[5] += w0 * a1.y + w1 * c1.y;
            acc[6] += w0 * a1.z + w1 * c1.z; acc[7] += w0 * a1.w + w1 * c1.w;
        } else {
            const float2* h0 = reinterpret_cast<const float2*>(hlin + (size_t)s0 * HCv + lane * 2);
            const float2* h1 = reinterpret_cast<const float2*>(hlin + (size_t)s1 * HCv + lane * 2);
            float2 a = h0[0], b = h1[0];
            acc[0] += w0 * a.x + w1 * b.x;
            acc[1] += w0 * a.y + w1 * b.y;
        }
    }
    if (p < end) {
        int s0 = __ldg(&csr_src[p]);
        float e0 = __ldg(&al_s[s0 * Hv + head]) + ald_h;
        e0 = (e0 > 0.f) ? e0 : SLOPE * e0;
        float w0 = __expf(e0);
        wsum += w0;
        if (CPL == 8) {
            const float4* h0 = reinterpret_cast<const float4*>(hlin + (size_t)s0 * HCv + lane * 8);
            float4 a0 = h0[0], a1 = h0[1];
            acc[0] += w0 * a0.x; acc[1] += w0 * a0.y; acc[2] += w0 * a0.z; acc[3] += w0 * a0.w;
            acc[4] += w0 * a1.x; acc[5] += w0 * a1.y; acc[6] += w0 * a1.z; acc[7] += w0 * a1.w;
        } else {
            const float2* h0 = reinterpret_cast<const float2*>(hlin + (size_t)s0 * HCv + lane * 2);
            float2 a = h0[0];
            acc[0] += w0 * a.x;
            acc[1] += w0 * a.y;
        }
    }

    float inv = 1.0f / (wsum + 1e-16f);
#pragma unroll
    for (int j = 0; j < CPL; j++) {
        int c = lane * CPL + j;
        float v = acc[j] * inv + bias[c];
        if (MODE == 0) {
            v = (v - mean[c]) * rsqrtf(var[c] + EPS_BN) * gamma[c] + beta[c];
        }
        v = (v > 0.f) ? v : 0.f;
        out[(size_t)gw * HCv + c] = v;
    }
}

// ---------------- mean pool ----------------
__global__ void pool_kernel(const float* __restrict__ h, const int* __restrict__ batch,
                            float* __restrict__ pooled, int* __restrict__ cnt) {
    int gw = (blockIdx.x * blockDim.x + threadIdx.x) >> 5;
    int lane = threadIdx.x & 31;
    if (gw >= NN) return;
    int b = batch[gw];
#pragma unroll
    for (int j = 0; j < 2; j++) {
        int c = lane + 32 * j;
        atomicAdd(&pooled[b * HC3 + c], h[(size_t)gw * HC3 + c]);
    }
    if (lane == 0) atomicAdd(&cnt[b], 1);
}

// ---------------- final MLP ----------------
__global__ void mlp_kernel(const float* __restrict__ pooled, const int* __restrict__ cnt,
                           const float* __restrict__ w1, const float* __restrict__ b1,
                           const float* __restrict__ w2, const float* __restrict__ b2,
                           float* __restrict__ out) {
    int g = blockIdx.x;
    int t = threadIdx.x;
    __shared__ float m[HC3];
    __shared__ float hid[32];
    float c = (float)cnt[g];
    if (c < 1.0f) c = 1.0f;
    m[t] = pooled[g * HC3 + t] / c;
    __syncthreads();
    if (t < 32) {
        float s = b1[t];
#pragma unroll
        for (int k = 0; k < HC3; k++) s += m[k] * w1[k * 32 + t];
        hid[t] = (s > 0.f) ? s : 0.f;
    }
    __syncthreads();
    if (t < NCLASS) {
        float s = b2[t];
#pragma unroll
        for (int k = 0; k < 32; k++) s += hid[k] * w2[k * NCLASS + t];
        out[g * NCLASS + t] = s;
    }
}

// ---------------- host orchestration ----------------
extern "C" void kernel_launch(void* const* d_in, const int* in_sizes, int n_in,
                              void* d_out, int out_size) {
    const float* x     = (const float*)d_in[0];
    const int*   ei    = (const int*)  d_in[1];
    const int*   batch = (const int*)  d_in[2];
    const float* W1    = (const float*)d_in[3];
    const float* a1s   = (const float*)d_in[4];
    const float* a1d   = (const float*)d_in[5];
    const float* b1    = (const float*)d_in[6];
    const float* bn1g  = (const float*)d_in[7];
    const float* bn1b  = (const float*)d_in[8];
    const float* bn1m  = (const float*)d_in[9];
    const float* bn1v  = (const float*)d_in[10];
    const float* W2    = (const float*)d_in[11];
    const float* a2s   = (const float*)d_in[12];
    const float* a2d   = (const float*)d_in[13];
    const float* b2    = (const float*)d_in[14];
    const float* bn2g  = (const float*)d_in[15];
    const float* bn2b  = (const float*)d_in[16];
    const float* bn2m  = (const float*)d_in[17];
    const float* bn2v  = (const float*)d_in[18];
    const float* W3    = (const float*)d_in[19];
    const float* a3s   = (const float*)d_in[20];
    const float* a3d   = (const float*)d_in[21];
    const float* b3    = (const float*)d_in[22];
    const float* lin1w = (const float*)d_in[23];
    const float* lin1b = (const float*)d_in[24];
    const float* lin2w = (const float*)d_in[25];
    const float* lin2b = (const float*)d_in[26];
    float* out = (float*)d_out;

    float *hlin, *hagg, *als, *ald, *pooled;
    int *counts, *rowptr, *csr_src, *bsums, *cnt;
    cudaGetSymbolAddress((void**)&hlin,    g_hlin);
    cudaGetSymbolAddress((void**)&hagg,    g_hagg);
    cudaGetSymbolAddress((void**)&als,     g_als);
    cudaGetSymbolAddress((void**)&ald,     g_ald);
    cudaGetSymbolAddress((void**)&pooled,  g_pooled);
    cudaGetSymbolAddress((void**)&counts,  g_counts);
    cudaGetSymbolAddress((void**)&rowptr,  g_rowptr);
    cudaGetSymbolAddress((void**)&csr_src, g_csr_src);
    cudaGetSymbolAddress((void**)&bsums,   g_bsums);
    cudaGetSymbolAddress((void**)&cnt,     g_cnt);

    const int TB = 256;
    const int edgeBlocks = cdiv(ETOT, TB);
    const int nodeWarpBlocks = cdiv(NN * 32, TB);

    // ---- CSR build ----
    zero_counts<<<cdiv(NN, TB), TB>>>(counts);
    hist_kernel<<<edgeBlocks, TB>>>(ei, counts);
    scan_pass1<<<NBLK1, 256>>>(counts, rowptr, bsums);
    scan_pass2<<<1, 128>>>(bsums);
    scan_pass3<<<NBLK1, 256>>>(rowptr, bsums);
    scatter_kernel<<<edgeBlocks, TB>>>(ei, rowptr, counts, csr_src);

    // ---- Layer 1 ----
    {
        dim3 grid(HC12 / 128, cdiv(NN, 128));
        gemm_attn<128, 2, 4, 4><<<grid, 256>>>(x, W1, hlin, a1s, a1d, als, ald, NN, HC12, FIN);
        gat_aggregate_kernel<HC12, 4, 0><<<nodeWarpBlocks, TB>>>(
            hlin, rowptr, csr_src, als, ald, b1, bn1g, bn1b, bn1m, bn1v, hagg);
    }
    // ---- Layer 2 ----
    {
        dim3 grid(HC12 / 128, cdiv(NN, 128));
        gemm_attn<128, 2, 4, 4><<<grid, 256>>>(hagg, W2, hlin, a2s, a2d, als, ald, NN, HC12, HC12);
        gat_aggregate_kernel<HC12, 4, 0><<<nodeWarpBlocks, TB>>>(
            hlin, rowptr, csr_src, als, ald, b2, bn2g, bn2b, bn2m, bn2v, hagg);
    }
    // ---- Layer 3 ----
    {
        dim3 grid(HC3 / 64, cdiv(NN, 128));
        gemm_attn<64, 4, 2, 1><<<grid, 256>>>(hagg, W3, hlin, a3s, a3d, als, ald, NN, HC3, HC12);
        gat_aggregate_kernel<HC3, 1, 1><<<nodeWarpBlocks, TB>>>(
            hlin, rowptr, csr_src, als, ald, b3, nullptr, nullptr, nullptr, nullptr, hagg);
    }
    // ---- Pool + MLP ----
    pool_zero<<<cdiv(NGRAPH * HC3, TB), TB>>>(pooled, cnt);
    pool_kernel<<<nodeWarpBlocks, TB>>>(hagg, batch, pooled, cnt);
    mlp_kernel<<<NGRAPH, HC3>>>(pooled, cnt, lin1w, lin1b, lin2w, lin2b, out);

    (void)in_sizes; (void)n_in; (void)out_size;
}

// round 8
// speedup vs baseline: 2.4270x; 1.0939x over previous
#include <cuda_runtime.h>
#include <cuda_fp16.h>
#include <cuda_bf16.h>
#include <cstdint>
#include <math.h>

// ---------------- problem constants ----------------
#define NN      20000
#define EDG     320000
#define ETOT    (EDG + NN)
#define FIN     512
#define HC12    256
#define HC3     64
#define NGRAPH  64
#define NCLASS  5
#define SLOPE   0.2f
#define EPS_BN  1e-5f
#define NBLK1   ((NN + 255) / 256)

#define W1SZ    (FIN * HC12)            // 131072
#define W2SZ    (HC12 * HC12)           // 65536
#define W3SZ    (HC12 * HC3)            // 16384
#define WTOT    (W1SZ + W2SZ + W3SZ)    // 212992

// ---------------- device scratch ----------------
__device__ __half g_hlin[(size_t)NN * HC12];    // GEMM output (gather-only) in fp16
__device__ float  g_hagg[(size_t)NN * HC12];
__device__ float  g_als[NN * 4];
__device__ float  g_ald[NN * 4];
__device__ float  g_wt[WTOT];                    // tf32-prerounded weights
__device__ int    g_counts[NN];
__device__ int    g_rowptr[NN + 1];
__device__ int    g_csr_src[ETOT];
__device__ int    g_bsums[128];
__device__ float  g_pooled[NGRAPH * HC3];
__device__ int    g_cnt[NGRAPH];

static inline int cdiv(int a, int b) { return (a + b - 1) / b; }

// round-to-nearest tf32 (returns fp32 bit pattern with low mantissa zeroed)
__device__ __forceinline__ unsigned f2tf(float x) {
    unsigned u;
    asm("cvt.rna.tf32.f32 %0, %1;" : "=r"(u) : "f"(x));
    return u;
}

// ---------------- prep: zero counts/pooled/cnt + preround W1/W2/W3 ----------------
__global__ void prep_kernel(const float* __restrict__ W1, const float* __restrict__ W2,
                            const float* __restrict__ W3, float* __restrict__ wt,
                            int* __restrict__ counts, float* __restrict__ pooled,
                            int* __restrict__ cnt) {
    int i = blockIdx.x * blockDim.x + threadIdx.x;
    if (i < WTOT) {
        float v;
        if (i < W1SZ)             v = W1[i];
        else if (i < W1SZ + W2SZ) v = W2[i - W1SZ];
        else                      v = W3[i - W1SZ - W2SZ];
        wt[i] = __uint_as_float(f2tf(v));
    }
    if (i < NN) counts[i] = 0;
    if (i < NGRAPH * HC3) pooled[i] = 0.0f;
    if (i < NGRAPH) cnt[i] = 0;
}

// ---------------- CSR build ----------------
__global__ void hist_kernel(const int* __restrict__ ei, int* __restrict__ counts) {
    int e = blockIdx.x * blockDim.x + threadIdx.x;
    if (e >= ETOT) return;
    int d = (e < EDG) ? ei[EDG + e] : (e - EDG);
    atomicAdd(&counts[d], 1);
}

__global__ void scan_pass1(const int* __restrict__ counts, int* __restrict__ rowptr,
                           int* __restrict__ bsums) {
    __shared__ int wsum[8];
    int b = blockIdx.x, t = threadIdx.x;
    int i = b * 256 + t;
    int x = (i < NN) ? counts[i] : 0;
#pragma unroll
    for (int o = 1; o < 32; o <<= 1) {
        int y = __shfl_up_sync(0xffffffffu, x, o);
        if ((t & 31) >= o) x += y;
    }
    if ((t & 31) == 31) wsum[t >> 5] = x;
    __syncthreads();
    if (t < 8) {
        int y = wsum[t];
#pragma unroll
        for (int o = 1; o < 8; o <<= 1) {
            int z = __shfl_up_sync(0xffu, y, o);
            if (t >= o) y += z;
        }
        wsum[t] = y;
    }
    __syncthreads();
    int off = (t >= 32) ? wsum[(t >> 5) - 1] : 0;
    int incl = x + off;
    if (i < NN) rowptr[i + 1] = incl;
    if (t == 255) bsums[b] = incl;
}
__global__ void scan_pass2(int* bsums) {
    __shared__ int wsum[4];
    int t = threadIdx.x;
    int x = (t < NBLK1) ? bsums[t] : 0;
#pragma unroll
    for (int o = 1; o < 32; o <<= 1) {
        int y = __shfl_up_sync(0xffffffffu, x, o);
        if ((t & 31) >= o) x += y;
    }
    if ((t & 31) == 31) wsum[t >> 5] = x;
    __syncthreads();
    if (t < 4) {
        int y = wsum[t];
#pragma unroll
        for (int o = 1; o < 4; o <<= 1) {
            int z = __shfl_up_sync(0xfu, y, o);
            if (t >= o) y += z;
        }
        wsum[t] = y;
    }
    __syncthreads();
    int off = (t >= 32) ? wsum[(t >> 5) - 1] : 0;
    if (t < NBLK1) bsums[t] = x + off;
}
__global__ void scan_pass3(int* __restrict__ rowptr, const int* __restrict__ bsums) {
    int b = blockIdx.x, t = threadIdx.x;
    if (b == 0) { if (t == 0) rowptr[0] = 0; return; }
    int i = b * 256 + t;
    int off = bsums[b - 1];
    if (i < NN) rowptr[i + 1] += off;
}

__global__ void scatter_kernel(const int* __restrict__ ei,
                               const int* __restrict__ rowptr,
                               int* __restrict__ counts,
                               int* __restrict__ csr_src) {
    int e = blockIdx.x * blockDim.x + threadIdx.x;
    if (e >= ETOT) return;
    int s, d;
    if (e < EDG) { s = ei[e]; d = ei[EDG + e]; }
    else         { s = d = e - EDG; }
    int pos = rowptr[d] + atomicSub(&counts[d], 1) - 1;
    csr_src[pos] = s;
}

// ---------------- cp.async helpers ----------------
__device__ __forceinline__ void cpa16(unsigned int dst, const void* src) {
    asm volatile("cp.async.cg.shared.global [%0], [%1], 16;\n" :: "r"(dst), "l"(src));
}
__device__ __forceinline__ void cp_commit() { asm volatile("cp.async.commit_group;\n"); }
template <int Ngrp>
__device__ __forceinline__ void cp_wait() { asm volatile("cp.async.wait_group %0;\n" :: "n"(Ngrp)); }

__device__ __forceinline__ void mma_tf32(float* d, const unsigned* a, const unsigned* b) {
    asm volatile(
        "mma.sync.aligned.m16n8k8.row.col.f32.tf32.tf32.f32 "
        "{%0,%1,%2,%3}, {%4,%5,%6,%7}, {%8,%9}, {%0,%1,%2,%3};\n"
        : "+f"(d[0]), "+f"(d[1]), "+f"(d[2]), "+f"(d[3])
        : "r"(a[0]), "r"(a[1]), "r"(a[2]), "r"(a[3]), "r"(b[0]), "r"(b[1]));
}

// ---------------- tf32 GEMM (fp16 C out) + fused attention-logit epilogue ----------------
// A fp32 (cvt.rna per fragment), B pre-rounded tf32 (raw bit loads).
template <int BN, int WRM, int WRN, int Hv>
__global__ __launch_bounds__(256) void gemm_attn(const float* __restrict__ A,
                                                 const float* __restrict__ B,
                                                 __half* __restrict__ C,
                                                 const float* __restrict__ a_s,
                                                 const float* __restrict__ a_d,
                                                 float* __restrict__ al_s,
                                                 float* __restrict__ al_d,
                                                 int M, int N, int K) {
    constexpr int BM = 128, BK = 16;
    constexpr int WM = BM / WRM, WN = BN / WRN;
    constexpr int MT = WM / 16, NT = WN / 8;
    constexpr int AS = BK + 4;
    constexpr int BS = BN + 8;
    constexpr int NB4 = BN / 4;
    constexpr int BLDB = (BK * NB4 + 255) / 256;
    constexpr int HB = BN / 64;

    __shared__ float As[2][BM * AS];
    __shared__ float Bs[2][BK * BS];
    __shared__ float sS[BM * HB];
    __shared__ float sD[BM * HB];

    int tid = threadIdx.x, lane = tid & 31, wid = tid >> 5;
    int by = blockIdx.y * BM, bx = blockIdx.x * BN;
    int wm = (wid / WRN) * WM, wn = (wid % WRN) * WN;

    float acc[MT][NT][4];
#pragma unroll
    for (int i = 0; i < MT; i++)
#pragma unroll
        for (int j = 0; j < NT; j++)
#pragma unroll
            for (int r = 0; r < 4; r++) acc[i][j][r] = 0.0f;

    const int ntiles = K / BK;

    auto fetch = [&](int kt, int buf) {
        int k0 = kt * BK;
#pragma unroll
        for (int j = 0; j < 2; j++) {
            int i = tid + j * 256;
            int row = i >> 2, c4 = i & 3;
            int gr = by + row; if (gr >= M) gr = M - 1;
            unsigned int dst = (unsigned int)__cvta_generic_to_shared(&As[buf][row * AS + c4 * 4]);
            cpa16(dst, A + (size_t)gr * K + k0 + c4 * 4);
        }
#pragma unroll
        for (int j = 0; j < BLDB; j++) {
            int i = tid + j * 256;
            if (i < BK * NB4) {
                int row = i / NB4, c4 = i % NB4;
                unsigned int dst = (unsigned int)__cvta_generic_to_shared(&Bs[buf][row * BS + c4 * 4]);
                cpa16(dst, B + (size_t)(k0 + row) * N + bx + c4 * 4);
            }
        }
    };
    auto compute = [&](int buf) {
#pragma unroll
        for (int ks = 0; ks < BK; ks += 8) {
            unsigned af[MT][4], bf[NT][2];
#pragma unroll
            for (int mt = 0; mt < MT; mt++) {
                int r0 = wm + mt * 16 + (lane >> 2);
                int c0 = ks + (lane & 3);
                af[mt][0] = f2tf(As[buf][r0 * AS + c0]);
                af[mt][1] = f2tf(As[buf][(r0 + 8) * AS + c0]);
                af[mt][2] = f2tf(As[buf][r0 * AS + c0 + 4]);
                af[mt][3] = f2tf(As[buf][(r0 + 8) * AS + c0 + 4]);
            }
#pragma unroll
            for (int nt = 0; nt < NT; nt++) {
                int kk = ks + (lane & 3);
                int n0 = wn + nt * 8 + (lane >> 2);
                bf[nt][0] = __float_as_uint(Bs[buf][kk * BS + n0]);   // pre-rounded
                bf[nt][1] = __float_as_uint(Bs[buf][(kk + 4) * BS + n0]);
            }
#pragma unroll
            for (int mt = 0; mt < MT; mt++)
#pragma unroll
                for (int nt = 0; nt < NT; nt++)
                    mma_tf32(acc[mt][nt], af[mt], bf[nt]);
        }
    };

    fetch(0, 0);
    cp_commit();
    for (int kt = 0; kt < ntiles; kt++) {
        int buf = kt & 1;
        if (kt + 1 < ntiles) { fetch(kt + 1, buf ^ 1); cp_commit(); cp_wait<1>(); }
        else                 { cp_wait<0>(); }
        __syncthreads();
        compute(buf);
        __syncthreads();
    }

    // ---- store C (fp16) ----
#pragma unroll
    for (int mt = 0; mt < MT; mt++) {
#pragma unroll
        for (int nt = 0; nt < NT; nt++) {
            int r0 = by + wm + mt * 16 + (lane >> 2);
            int c0 = bx + wn + nt * 8 + 2 * (lane & 3);
            if (r0 < M)
                *reinterpret_cast<__half2*>(&C[(size_t)r0 * N + c0]) =
                    __floats2half2_rn(acc[mt][nt][0], acc[mt][nt][1]);
            if (r0 + 8 < M)
                *reinterpret_cast<__half2*>(&C[(size_t)(r0 + 8) * N + c0]) =
                    __floats2half2_rn(acc[mt][nt][2], acc[mt][nt][3]);
        }
    }

    // ---- fused attention-logit epilogue (fp32 from registers) ----
    for (int i = tid; i < BM * HB; i += 256) { sS[i] = 0.f; sD[i] = 0.f; }
    __syncthreads();

    float as0[NT], as1[NT], ad0[NT], ad1[NT];
#pragma unroll
    for (int nt = 0; nt < NT; nt++) {
        int c = bx + wn + nt * 8 + 2 * (lane & 3);
        as0[nt] = a_s[c]; as1[nt] = a_s[c + 1];
        ad0[nt] = a_d[c]; ad1[nt] = a_d[c + 1];
    }
    int hl = wn >> 6;
#pragma unroll
    for (int mt = 0; mt < MT; mt++) {
        float pslo = 0.f, pshi = 0.f, pdlo = 0.f, pdhi = 0.f;
#pragma unroll
        for (int nt = 0; nt < NT; nt++) {
            pslo += acc[mt][nt][0] * as0[nt] + acc[mt][nt][1] * as1[nt];
            pshi += acc[mt][nt][2] * as0[nt] + acc[mt][nt][3] * as1[nt];
            pdlo += acc[mt][nt][0] * ad0[nt] + acc[mt][nt][1] * ad1[nt];
            pdhi += acc[mt][nt][2] * ad0[nt] + acc[mt][nt][3] * ad1[nt];
        }
        pslo += __shfl_xor_sync(0xffffffffu, pslo, 1);
        pslo += __shfl_xor_sync(0xffffffffu, pslo, 2);
        pshi += __shfl_xor_sync(0xffffffffu, pshi, 1);
        pshi += __shfl_xor_sync(0xffffffffu, pshi, 2);
        pdlo += __shfl_xor_sync(0xffffffffu, pdlo, 1);
        pdlo += __shfl_xor_sync(0xffffffffu, pdlo, 2);
        pdhi += __shfl_xor_sync(0xffffffffu, pdhi, 1);
        pdhi += __shfl_xor_sync(0xffffffffu, pdhi, 2);
        if ((lane & 3) == 0) {
            int r = wm + mt * 16 + (lane >> 2);
            atomicAdd(&sS[r * HB + hl], pslo);
            atomicAdd(&sS[(r + 8) * HB + hl], pshi);
            atomicAdd(&sD[r * HB + hl], pdlo);
            atomicAdd(&sD[(r + 8) * HB + hl], pdhi);
        }
    }
    __syncthreads();
    int headbase = bx >> 6;
    for (int i = tid; i < BM * HB; i += 256) {
        int row = i / HB, h2 = i % HB;
        int gr = by + row;
        if (gr < M) {
            al_s[gr * Hv + headbase + h2] = sS[i];
            al_d[gr * Hv + headbase + h2] = sD[i];
        }
    }
}

// ---------------- aggregation (warp per dst), fp16 gathers, inline edge softmax ----------------
template <int HCv, int Hv, int MODE>
__global__ void gat_aggregate_kernel(const __half* __restrict__ hlin,
                                     const int* __restrict__ rowptr,
                                     const int* __restrict__ csr_src,
                                     const float* __restrict__ al_s,
                                     const float* __restrict__ al_d,
                                     const float* __restrict__ bias,
                                     const float* __restrict__ gamma,
                                     const float* __restrict__ beta,
                                     const float* __restrict__ mean,
                                     const float* __restrict__ var,
                                     float* __restrict__ out) {
    int gw = (blockIdx.x * blockDim.x + threadIdx.x) >> 5;
    int lane = threadIdx.x & 31;
    if (gw >= NN) return;
    const int CPL = HCv / 32;
    int head = (lane * CPL) >> 6;
    float acc[CPL];
#pragma unroll
    for (int j = 0; j < CPL; j++) acc[j] = 0.f;
    float wsum = 0.f;
    float ald_h = __ldg(&al_d[gw * Hv + head]);

    int beg = rowptr[gw], end = rowptr[gw + 1];
    int p = beg;
    for (; p + 2 <= end; p += 2) {
        int s0 = __ldg(&csr_src[p]);
        int s1 = __ldg(&csr_src[p + 1]);
        float e0 = __ldg(&al_s[s0 * Hv + head]) + ald_h;
        float e1 = __ldg(&al_s[s1 * Hv + head]) + ald_h;
        e0 = (e0 > 0.f) ? e0 : SLOPE * e0;
        e1 = (e1 > 0.f) ? e1 : SLOPE * e1;
        float w0 = __expf(e0), w1 = __expf(e1);
        wsum += w0 + w1;
        if (CPL == 8) {
            uint4 u0 = *reinterpret_cast<const uint4*>(hlin + (size_t)s0 * HCv + lane * 8);
            uint4 u1 = *reinterpret_cast<const uint4*>(hlin + (size_t)s1 * HCv + lane * 8);
            float2 f;
            f = __half22float2(*reinterpret_cast<__half2*>(&u0.x)); acc[0] += w0 * f.x; acc[1] += w0 * f.y;
            f = __half22float2(*reinterpret_cast<__half2*>(&u0.y)); acc[2] += w0 * f.x; acc[3] += w0 * f.y;
            f = __half22float2(*reinterpret_cast<__half2*>(&u0.z)); acc[4] += w0 * f.x; acc[5] += w0 * f.y;
            f = __half22float2(*reinterpret_cast<__half2*>(&u0.w)); acc[6] += w0 * f.x; acc[7] += w0 * f.y;
            f = __half22float2(*reinterpret_cast<__half2*>(&u1.x)); acc[0] += w1 * f.x; acc[1] += w1 * f.y;
            f = __half22float2(*reinterpret_cast<__half2*>(&u1.y)); acc[2] += w1 * f.x; acc[3] += w1 * f.y;
            f = __half22float2(*reinterpret_cast<__half2*>(&u1.z)); acc[4] += w1 * f.x; acc[5] += w1 * f.y;
            f = __half22float2(*reinterpret_cast<__half2*>(&u1.w)); acc[6] += w1 * f.x; acc[7] += w1 * f.y;
        } else {
            float2 a = __half22float2(*reinterpret_cast<const __half2*>(hlin + (size_t)s0 * HCv + lane * 2));
            float2 b = __half22float2(*reinterpret_cast<const __half2*>(hlin + (size_t)s1 * HCv + lane * 2));
            acc[0] += w0 * a.x + w1 * b.x;
            acc[1] += w0 * a.y + w1 * b.y;
        }
    }
    if (p < end) {
        int s0 = __ldg(&csr_src[p]);
        float e0 = __ldg(&al_s[s0 * Hv + head]) + ald_h;
        e0 = (e0 > 0.f) ? e0 : SLOPE * e0;
        float w0 = __expf(e0);
        wsum += w0;
        if (CPL == 8) {
            uint4 u0 = *reinterpret_cast<const uint4*>(hlin + (size_t)s0 * HCv + lane * 8);
            float2 f;
            f = __half22float2(*reinterpret_cast<__half2*>(&u0.x)); acc[0] += w0 * f.x; acc[1] += w0 * f.y;
            f = __half22float2(*reinterpret_cast<__half2*>(&u0.y)); acc[2] += w0 * f.x; acc[3] += w0 * f.y;
            f = __half22float2(*reinterpret_cast<__half2*>(&u0.z)); acc[4] += w0 * f.x; acc[5] += w0 * f.y;
            f = __half22float2(*reinterpret_cast<__half2*>(&u0.w)); acc[6] += w0 * f.x; acc[7] += w0 * f.y;
        } else {
            float2 a = __half22float2(*reinterpret_cast<const __half2*>(hlin + (size_t)s0 * HCv + lane * 2));
            acc[0] += w0 * a.x;
            acc[1] += w0 * a.y;
        }
    }

    float inv = 1.0f / (wsum + 1e-16f);
#pragma unroll
    for (int j = 0; j < CPL; j++) {
        int c = lane * CPL + j;
        float v = acc[j] * inv + bias[c];
        if (MODE == 0) {
            v = (v - mean[c]) * rsqrtf(var[c] + EPS_BN) * gamma[c] + beta[c];
        }
        v = (v > 0.f) ? v : 0.f;
        out[(size_t)gw * HCv + c] = v;
    }
}

// ---------------- mean pool ----------------
__global__ void pool_kernel(const float* __restrict__ h, const int* __restrict__ batch,
                            float* __restrict__ pooled, int* __restrict__ cnt) {
    int gw = (blockIdx.x * blockDim.x + threadIdx.x) >> 5;
    int lane = threadIdx.x & 31;
    if (gw >= NN) return;
    int b = batch[gw];
#pragma unroll
    for (int j = 0; j < 2; j++) {
        int c = lane + 32 * j;
        atomicAdd(&pooled[b * HC3 + c], h[(size_t)gw * HC3 + c]);
    }
    if (lane == 0) atomicAdd(&cnt[b], 1);
}

// ---------------- final MLP ----------------
__global__ void mlp_kernel(const float* __restrict__ pooled, const int* __restrict__ cnt,
                           const float* __restrict__ w1, const float* __restrict__ b1,
                           const float* __restrict__ w2, const float* __restrict__ b2,
                           float* __restrict__ out) {
    int g = blockIdx.x;
    int t = threadIdx.x;
    __shared__ float m[HC3];
    __shared__ float hid[32];
    float c = (float)cnt[g];
    if (c < 1.0f) c = 1.0f;
    m[t] = pooled[g * HC3 + t] / c;
    __syncthreads();
    if (t < 32) {
        float s = b1[t];
#pragma unroll
        for (int k = 0; k < HC3; k++) s += m[k] * w1[k * 32 + t];
        hid[t] = (s > 0.f) ? s : 0.f;
    }
    __syncthreads();
    if (t < NCLASS) {
        float s = b2[t];
#pragma unroll
        for (int k = 0; k < 32; k++) s += hid[k] * w2[k * NCLASS + t];
        out[g * NCLASS + t] = s;
    }
}

// ---------------- host orchestration ----------------
extern "C" void kernel_launch(void* const* d_in, const int* in_sizes, int n_in,
                              void* d_out, int out_size) {
    const float* x     = (const float*)d_in[0];
    const int*   ei    = (const int*)  d_in[1];
    const int*   batch = (const int*)  d_in[2];
    const float* W1    = (const float*)d_in[3];
    const float* a1s   = (const float*)d_in[4];
    const float* a1d   = (const float*)d_in[5];
    const float* b1    = (const float*)d_in[6];
    const float* bn1g  = (const float*)d_in[7];
    const float* bn1b  = (const float*)d_in[8];
    const float* bn1m  = (const float*)d_in[9];
    const float* bn1v  = (const float*)d_in[10];
    const float* W2    = (const float*)d_in[11];
    const float* a2s   = (const float*)d_in[12];
    const float* a2d   = (const float*)d_in[13];
    const float* b2    = (const float*)d_in[14];
    const float* bn2g  = (const float*)d_in[15];
    const float* bn2b  = (const float*)d_in[16];
    const float* bn2m  = (const float*)d_in[17];
    const float* bn2v  = (const float*)d_in[18];
    const float* W3    = (const float*)d_in[19];
    const float* a3s   = (const float*)d_in[20];
    const float* a3d   = (const float*)d_in[21];
    const float* b3    = (const float*)d_in[22];
    const float* lin1w = (const float*)d_in[23];
    const float* lin1b = (const float*)d_in[24];
    const float* lin2w = (const float*)d_in[25];
    const float* lin2b = (const float*)d_in[26];
    float* out = (float*)d_out;

    __half* hlin;
    float *hagg, *als, *ald, *wt, *pooled;
    int *counts, *rowptr, *csr_src, *bsums, *cnt;
    cudaGetSymbolAddress((void**)&hlin,    g_hlin);
    cudaGetSymbolAddress((void**)&hagg,    g_hagg);
    cudaGetSymbolAddress((void**)&als,     g_als);
    cudaGetSymbolAddress((void**)&ald,     g_ald);
    cudaGetSymbolAddress((void**)&wt,      g_wt);
    cudaGetSymbolAddress((void**)&pooled,  g_pooled);
    cudaGetSymbolAddress((void**)&counts,  g_counts);
    cudaGetSymbolAddress((void**)&rowptr,  g_rowptr);
    cudaGetSymbolAddress((void**)&csr_src, g_csr_src);
    cudaGetSymbolAddress((void**)&bsums,   g_bsums);
    cudaGetSymbolAddress((void**)&cnt,     g_cnt);

    const int TB = 256;
    const int edgeBlocks = cdiv(ETOT, TB);
    const int nodeWarpBlocks = cdiv(NN * 32, TB);

    // launch order arranged so ncu (-s 5 -c 1) captures the layer-1 GEMM (index 5)
    // 0: prep (zero counts/pooled/cnt + preround W)
    prep_kernel<<<cdiv(WTOT, TB), TB>>>(W1, W2, W3, wt, counts, pooled, cnt);
    // 1-4: CSR histogram + scan
    hist_kernel<<<edgeBlocks, TB>>>(ei, counts);
    scan_pass1<<<NBLK1, 256>>>(counts, rowptr, bsums);
    scan_pass2<<<1, 128>>>(bsums);
    scan_pass3<<<NBLK1, 256>>>(rowptr, bsums);
    // 5: layer-1 GEMM (independent of CSR) — profiled launch
    {
        dim3 grid(HC12 / 128, cdiv(NN, 128));
        gemm_attn<128, 2, 4, 4><<<grid, 256>>>(x, wt, hlin, a1s, a1d, als, ald, NN, HC12, FIN);
    }
    // 6: CSR scatter
    scatter_kernel<<<edgeBlocks, TB>>>(ei, rowptr, counts, csr_src);
    // 7: layer-1 aggregate
    gat_aggregate_kernel<HC12, 4, 0><<<nodeWarpBlocks, TB>>>(
        hlin, rowptr, csr_src, als, ald, b1, bn1g, bn1b, bn1m, bn1v, hagg);
    // 8-9: layer 2
    {
        dim3 grid(HC12 / 128, cdiv(NN, 128));
        gemm_attn<128, 2, 4, 4><<<grid, 256>>>(hagg, wt + W1SZ, hlin, a2s, a2d, als, ald, NN, HC12, HC12);
        gat_aggregate_kernel<HC12, 4, 0><<<nodeWarpBlocks, TB>>>(
            hlin, rowptr, csr_src, als, ald, b2, bn2g, bn2b, bn2m, bn2v, hagg);
    }
    // 10-11: layer 3
    {
        dim3 grid(HC3 / 64, cdiv(NN, 128));
        gemm_attn<64, 4, 2, 1><<<grid, 256>>>(hagg, wt + W1SZ + W2SZ, hlin, a3s, a3d, als, ald, NN, HC3, HC12);
        gat_aggregate_kernel<HC3, 1, 1><<<nodeWarpBlocks, TB>>>(
            hlin, rowptr, csr_src, als, ald, b3, nullptr, nullptr, nullptr, nullptr, hagg);
    }
    // 12-13: pool + MLP
    pool_kernel<<<nodeWarpBlocks, TB>>>(hagg, batch, pooled, cnt);
    mlp_kernel<<<NGRAPH, HC3>>>(pooled, cnt, lin1w, lin1b, lin2w, lin2b, out);

    (void)in_sizes; (void)n_in; (void)out_size;
}

// round 9
// speedup vs baseline: 2.7936x; 1.1511x over previous
#include <cuda_runtime.h>
#include <cuda_fp16.h>
#include <cstdint>
#include <math.h>

// ---------------- problem constants ----------------
#define NN      20000
#define EDG     320000
#define ETOT    (EDG + NN)
#define FIN     512
#define HC12    256
#define HC3     64
#define NGRAPH  64
#define NCLASS  5
#define SLOPE   0.2f
#define EPS_BN  1e-5f
#define NBLK1   ((NN + 255) / 256)

#define W1SZ    (FIN * HC12)
#define W2SZ    (HC12 * HC12)
#define W3SZ    (HC12 * HC3)
#define WTOT    (W1SZ + W2SZ + W3SZ)
#define XHSZ    (NN * FIN)

// ---------------- device scratch ----------------
__device__ __half g_xh[(size_t)XHSZ];           // x in fp16
__device__ __half g_hlin[(size_t)NN * HC12];    // GEMM output (gather source)
__device__ __half g_hagg[(size_t)NN * HC12];    // layer output (next GEMM's A)
__device__ float  g_als[NN * 4];
__device__ float  g_ald[NN * 4];
__device__ __half g_wt[WTOT];                   // weights, transposed [N][K], fp16
__device__ int    g_counts[NN];
__device__ int    g_rowptr[NN + 1];
__device__ int    g_csr_src[ETOT];
__device__ int    g_bsums[128];
__device__ float  g_pooled[NGRAPH * HC3];
__device__ int    g_cnt[NGRAPH];

static inline int cdiv(int a, int b) { return (a + b - 1) / b; }

// ---------------- prep: x->fp16, W transpose->fp16, zero counters ----------------
__global__ void prep_kernel(const float* __restrict__ x,
                            const float* __restrict__ W1, const float* __restrict__ W2,
                            const float* __restrict__ W3, __half* __restrict__ wt,
                            __half* __restrict__ xh,
                            int* __restrict__ counts, float* __restrict__ pooled,
                            int* __restrict__ cnt) {
    int i = blockIdx.x * blockDim.x + threadIdx.x;
    if (i < XHSZ) xh[i] = __float2half(x[i]);
    if (i < W1SZ) {                       // W1 [512,256] -> w1t [256][512]
        int k = i / HC12, n = i % HC12;
        wt[n * FIN + k] = __float2half(W1[i]);
    } else if (i < W1SZ + W2SZ) {         // W2 [256,256] -> [256][256]
        int j = i - W1SZ;
        int k = j / HC12, n = j % HC12;
        wt[W1SZ + n * HC12 + k] = __float2half(W2[j]);
    } else if (i < WTOT) {                // W3 [256,64] -> [64][256]
        int j = i - W1SZ - W2SZ;
        int k = j / HC3, n = j % HC3;
        wt[W1SZ + W2SZ + n * HC12 + k] = __float2half(W3[j]);
    }
    if (i < NN) counts[i] = 0;
    if (i < NGRAPH * HC3) pooled[i] = 0.0f;
    if (i < NGRAPH) cnt[i] = 0;
}

// ---------------- CSR build ----------------
__global__ void hist_kernel(const int* __restrict__ ei, int* __restrict__ counts) {
    int e = blockIdx.x * blockDim.x + threadIdx.x;
    if (e >= ETOT) return;
    int d = (e < EDG) ? ei[EDG + e] : (e - EDG);
    atomicAdd(&counts[d], 1);
}

__global__ void scan_pass1(const int* __restrict__ counts, int* __restrict__ rowptr,
                           int* __restrict__ bsums) {
    __shared__ int wsum[8];
    int b = blockIdx.x, t = threadIdx.x;
    int i = b * 256 + t;
    int x = (i < NN) ? counts[i] : 0;
#pragma unroll
    for (int o = 1; o < 32; o <<= 1) {
        int y = __shfl_up_sync(0xffffffffu, x, o);
        if ((t & 31) >= o) x += y;
    }
    if ((t & 31) == 31) wsum[t >> 5] = x;
    __syncthreads();
    if (t < 8) {
        int y = wsum[t];
#pragma unroll
        for (int o = 1; o < 8; o <<= 1) {
            int z = __shfl_up_sync(0xffu, y, o);
            if (t >= o) y += z;
        }
        wsum[t] = y;
    }
    __syncthreads();
    int off = (t >= 32) ? wsum[(t >> 5) - 1] : 0;
    int incl = x + off;
    if (i < NN) rowptr[i + 1] = incl;
    if (t == 255) bsums[b] = incl;
}

// merged pass2+pass3: each block reduces its own bsums prefix
__global__ void scan_fixup(int* __restrict__ rowptr, const int* __restrict__ bsums) {
    int b = blockIdx.x, t = threadIdx.x;
    if (b == 0) { if (t == 0) rowptr[0] = 0; return; }
    __shared__ int red[8];
    int v = 0;
    for (int j = t; j < b; j += 256) v += bsums[j];
#pragma unroll
    for (int o = 16; o; o >>= 1) v += __shfl_down_sync(0xffffffffu, v, o);
    if ((t & 31) == 0) red[t >> 5] = v;
    __syncthreads();
    if (t < 8) {
        int y = red[t];
#pragma unroll
        for (int o = 4; o; o >>= 1) y += __shfl_down_sync(0xffu, y, o);
        if (t == 0) red[0] = y;
    }
    __syncthreads();
    int off = red[0];
    int i = b * 256 + t;
    if (i < NN) rowptr[i + 1] += off;
}

__global__ void scatter_kernel(const int* __restrict__ ei,
                               const int* __restrict__ rowptr,
                               int* __restrict__ counts,
                               int* __restrict__ csr_src) {
    int e = blockIdx.x * blockDim.x + threadIdx.x;
    if (e >= ETOT) return;
    int s, d;
    if (e < EDG) { s = ei[e]; d = ei[EDG + e]; }
    else         { s = d = e - EDG; }
    int pos = rowptr[d] + atomicSub(&counts[d], 1) - 1;
    csr_src[pos] = s;
}

// ---------------- cp.async helpers ----------------
__device__ __forceinline__ void cpa16(unsigned int dst, const void* src) {
    asm volatile("cp.async.cg.shared.global [%0], [%1], 16;\n" :: "r"(dst), "l"(src));
}
__device__ __forceinline__ void cp_commit() { asm volatile("cp.async.commit_group;\n"); }
template <int Ngrp>
__device__ __forceinline__ void cp_wait() { asm volatile("cp.async.wait_group %0;\n" :: "n"(Ngrp)); }

__device__ __forceinline__ void mma_f16(float* d, const unsigned* a, const unsigned* b) {
    asm volatile(
        "mma.sync.aligned.m16n8k16.row.col.f32.f16.f16.f32 "
        "{%0,%1,%2,%3}, {%4,%5,%6,%7}, {%8,%9}, {%0,%1,%2,%3};\n"
        : "+f"(d[0]), "+f"(d[1]), "+f"(d[2]), "+f"(d[3])
        : "r"(a[0]), "r"(a[1]), "r"(a[2]), "r"(a[3]), "r"(b[0]), "r"(b[1]));
}

// ---------------- fp16 GEMM + fused attention-logit epilogue ----------------
// A [M,K] fp16 row-major; B [N,K] fp16 (transposed weights); C [M,N] fp16.
template <int BN, int WRM, int WRN, int Hv>
__global__ __launch_bounds__(256) void gemm_attn(const __half* __restrict__ A,
                                                 const __half* __restrict__ B,
                                                 __half* __restrict__ C,
                                                 const float* __restrict__ a_s,
                                                 const float* __restrict__ a_d,
                                                 float* __restrict__ al_s,
                                                 float* __restrict__ al_d,
                                                 int M, int N, int K) {
    constexpr int BM = 128, BK = 32;
    constexpr int WM = BM / WRM, WN = BN / WRN;
    constexpr int MT = WM / 16, NT = WN / 8;
    constexpr int AS = BK + 8;                 // padded stride in halves (40)
    constexpr int ACH = BM * 4;                // A 16B chunks per tile (512)
    constexpr int BCH = BN * 4;                // B 16B chunks per tile
    constexpr int BLDB = (BCH + 255) / 256;
    constexpr int HB = BN / 64;

    __shared__ __half As[2][BM * AS];
    __shared__ __half Bs[2][BN * AS];
    __shared__ float sS[BM * HB];
    __shared__ float sD[BM * HB];

    int tid = threadIdx.x, lane = tid & 31, wid = tid >> 5;
    int by = blockIdx.y * BM, bx = blockIdx.x * BN;
    int wm = (wid / WRN) * WM, wn = (wid % WRN) * WN;

    float acc[MT][NT][4];
#pragma unroll
    for (int i = 0; i < MT; i++)
#pragma unroll
        for (int j = 0; j < NT; j++)
#pragma unroll
            for (int r = 0; r < 4; r++) acc[i][j][r] = 0.0f;

    const int ntiles = K / BK;

    auto fetch = [&](int kt, int buf) {
        int k0 = kt * BK;
#pragma unroll
        for (int j = 0; j < ACH / 256; j++) {
            int i = tid + j * 256;
            int row = i >> 2, c = i & 3;
            int gr = by + row; if (gr >= M) gr = M - 1;
            unsigned int dst = (unsigned int)__cvta_generic_to_shared(&As[buf][row * AS + c * 8]);
            cpa16(dst, A + (size_t)gr * K + k0 + c * 8);
        }
#pragma unroll
        for (int j = 0; j < BLDB; j++) {
            int i = tid + j * 256;
            if (i < BCH) {
                int row = i >> 2, c = i & 3;
                unsigned int dst = (unsigned int)__cvta_generic_to_shared(&Bs[buf][row * AS + c * 8]);
                cpa16(dst, B + (size_t)(bx + row) * K + k0 + c * 8);
            }
        }
    };
    auto compute = [&](int buf) {
#pragma unroll
        for (int ks = 0; ks < BK; ks += 16) {
            int c0 = ks + 2 * (lane & 3);
            unsigned af[MT][4], bf[NT][2];
#pragma unroll
            for (int mt = 0; mt < MT; mt++) {
                int r0 = wm + mt * 16 + (lane >> 2);
                af[mt][0] = *reinterpret_cast<const unsigned*>(&As[buf][r0 * AS + c0]);
                af[mt][1] = *reinterpret_cast<const unsigned*>(&As[buf][(r0 + 8) * AS + c0]);
                af[mt][2] = *reinterpret_cast<const unsigned*>(&As[buf][r0 * AS + c0 + 8]);
                af[mt][3] = *reinterpret_cast<const unsigned*>(&As[buf][(r0 + 8) * AS + c0 + 8]);
            }
#pragma unroll
            for (int nt = 0; nt < NT; nt++) {
                int n0 = wn + nt * 8 + (lane >> 2);
                bf[nt][0] = *reinterpret_cast<const unsigned*>(&Bs[buf][n0 * AS + c0]);
                bf[nt][1] = *reinterpret_cast<const unsigned*>(&Bs[buf][n0 * AS + c0 + 8]);
            }
#pragma unroll
            for (int mt = 0; mt < MT; mt++)
#pragma unroll
                for (int nt = 0; nt < NT; nt++)
                    mma_f16(acc[mt][nt], af[mt], bf[nt]);
        }
    };

    fetch(0, 0);
    cp_commit();
    for (int kt = 0; kt < ntiles; kt++) {
        int buf = kt & 1;
        if (kt + 1 < ntiles) { fetch(kt + 1, buf ^ 1); cp_commit(); cp_wait<1>(); }
        else                 { cp_wait<0>(); }
        __syncthreads();
        compute(buf);
        __syncthreads();
    }

    // ---- store C (fp16) ----
#pragma unroll
    for (int mt = 0; mt < MT; mt++) {
#pragma unroll
        for (int nt = 0; nt < NT; nt++) {
            int r0 = by + wm + mt * 16 + (lane >> 2);
            int c0 = bx + wn + nt * 8 + 2 * (lane & 3);
            if (r0 < M)
                *reinterpret_cast<__half2*>(&C[(size_t)r0 * N + c0]) =
                    __floats2half2_rn(acc[mt][nt][0], acc[mt][nt][1]);
            if (r0 + 8 < M)
                *reinterpret_cast<__half2*>(&C[(size_t)(r0 + 8) * N + c0]) =
                    __floats2half2_rn(acc[mt][nt][2], acc[mt][nt][3]);
        }
    }

    // ---- fused attention-logit epilogue ----
    for (int i = tid; i < BM * HB; i += 256) { sS[i] = 0.f; sD[i] = 0.f; }
    __syncthreads();

    float as0[NT], as1[NT], ad0[NT], ad1[NT];
#pragma unroll
    for (int nt = 0; nt < NT; nt++) {
        int c = bx + wn + nt * 8 + 2 * (lane & 3);
        as0[nt] = a_s[c]; as1[nt] = a_s[c + 1];
        ad0[nt] = a_d[c]; ad1[nt] = a_d[c + 1];
    }
    int hl = wn >> 6;
#pragma unroll
    for (int mt = 0; mt < MT; mt++) {
        float pslo = 0.f, pshi = 0.f, pdlo = 0.f, pdhi = 0.f;
#pragma unroll
        for (int nt = 0; nt < NT; nt++) {
            pslo += acc[mt][nt][0] * as0[nt] + acc[mt][nt][1] * as1[nt];
            pshi += acc[mt][nt][2] * as0[nt] + acc[mt][nt][3] * as1[nt];
            pdlo += acc[mt][nt][0] * ad0[nt] + acc[mt][nt][1] * ad1[nt];
            pdhi += acc[mt][nt][2] * ad0[nt] + acc[mt][nt][3] * ad1[nt];
        }
        pslo += __shfl_xor_sync(0xffffffffu, pslo, 1);
        pslo += __shfl_xor_sync(0xffffffffu, pslo, 2);
        pshi += __shfl_xor_sync(0xffffffffu, pshi, 1);
        pshi += __shfl_xor_sync(0xffffffffu, pshi, 2);
        pdlo += __shfl_xor_sync(0xffffffffu, pdlo, 1);
        pdlo += __shfl_xor_sync(0xffffffffu, pdlo, 2);
        pdhi += __shfl_xor_sync(0xffffffffu, pdhi, 1);
        pdhi += __shfl_xor_sync(0xffffffffu, pdhi, 2);
        if ((lane & 3) == 0) {
            int r = wm + mt * 16 + (lane >> 2);
            atomicAdd(&sS[r * HB + hl], pslo);
            atomicAdd(&sS[(r + 8) * HB + hl], pshi);
            atomicAdd(&sD[r * HB + hl], pdlo);
            atomicAdd(&sD[(r + 8) * HB + hl], pdhi);
        }
    }
    __syncthreads();
    int headbase = bx >> 6;
    for (int i = tid; i < BM * HB; i += 256) {
        int row = i / HB, h2 = i % HB;
        int gr = by + row;
        if (gr < M) {
            al_s[gr * Hv + headbase + h2] = sS[i];
            al_d[gr * Hv + headbase + h2] = sD[i];
        }
    }
}

// ---------------- aggregation (warp per dst), fp16 in, inline edge softmax ----------------
// MODE 0: bias+BN+ReLU -> fp16 out (layers 1,2). MODE 1: bias+ReLU -> fused mean-pool atomics.
template <int HCv, int Hv, int MODE>
__global__ void gat_aggregate_kernel(const __half* __restrict__ hlin,
                                     const int* __restrict__ rowptr,
                                     const int* __restrict__ csr_src,
                                     const float* __restrict__ al_s,
                                     const float* __restrict__ al_d,
                                     const float* __restrict__ bias,
                                     const float* __restrict__ gamma,
                                     const float* __restrict__ beta,
                                     const float* __restrict__ mean,
                                     const float* __restrict__ var,
                                     __half* __restrict__ out,
                                     const int* __restrict__ batch,
                                     float* __restrict__ pooled,
                                     int* __restrict__ cnt) {
    int gw = (blockIdx.x * blockDim.x + threadIdx.x) >> 5;
    int lane = threadIdx.x & 31;
    if (gw >= NN) return;
    const int CPL = HCv / 32;
    int head = (lane * CPL) >> 6;
    float acc[CPL];
#pragma unroll
    for (int j = 0; j < CPL; j++) acc[j] = 0.f;
    float wsum = 0.f;
    float ald_h = __ldg(&al_d[gw * Hv + head]);

    int beg = rowptr[gw], end = rowptr[gw + 1];
    int p = beg;
    for (; p + 2 <= end; p += 2) {
        int s0 = __ldg(&csr_src[p]);
        int s1 = __ldg(&csr_src[p + 1]);
        float e0 = __ldg(&al_s[s0 * Hv + head]) + ald_h;
        float e1 = __ldg(&al_s[s1 * Hv + head]) + ald_h;
        e0 = (e0 > 0.f) ? e0 : SLOPE * e0;
        e1 = (e1 > 0.f) ? e1 : SLOPE * e1;
        float w0 = __expf(e0), w1 = __expf(e1);
        wsum += w0 + w1;
        if (CPL == 8) {
            uint4 u0 = *reinterpret_cast<const uint4*>(hlin + (size_t)s0 * HCv + lane * 8);
            uint4 u1 = *reinterpret_cast<const uint4*>(hlin + (size_t)s1 * HCv + lane * 8);
            float2 f;
            f = __half22float2(*reinterpret_cast<__half2*>(&u0.x)); acc[0] += w0 * f.x; acc[1] += w0 * f.y;
            f = __half22float2(*reinterpret_cast<__half2*>(&u0.y)); acc[2] += w0 * f.x; acc[3] += w0 * f.y;
            f = __half22float2(*reinterpret_cast<__half2*>(&u0.z)); acc[4] += w0 * f.x; acc[5] += w0 * f.y;
            f = __half22float2(*reinterpret_cast<__half2*>(&u0.w)); acc[6] += w0 * f.x; acc[7] += w0 * f.y;
            f = __half22float2(*reinterpret_cast<__half2*>(&u1.x)); acc[0] += w1 * f.x; acc[1] += w1 * f.y;
            f = __half22float2(*reinterpret_cast<__half2*>(&u1.y)); acc[2] += w1 * f.x; acc[3] += w1 * f.y;
            f = __half22float2(*reinterpret_cast<__half2*>(&u1.z)); acc[4] += w1 * f.x; acc[5] += w1 * f.y;
            f = __half22float2(*reinterpret_cast<__half2*>(&u1.w)); acc[6] += w1 * f.x; acc[7] += w1 * f.y;
        } else {
            float2 a = __half22float2(*reinterpret_cast<const __half2*>(hlin + (size_t)s0 * HCv + lane * 2));
            float2 b = __half22float2(*reinterpret_cast<const __half2*>(hlin + (size_t)s1 * HCv + lane * 2));
            acc[0] += w0 * a.x + w1 * b.x;
            acc[1] += w0 * a.y + w1 * b.y;
        }
    }
    if (p < end) {
        int s0 = __ldg(&csr_src[p]);
        float e0 = __ldg(&al_s[s0 * Hv + head]) + ald_h;
        e0 = (e0 > 0.f) ? e0 : SLOPE * e0;
        float w0 = __expf(e0);
        wsum += w0;
        if (CPL == 8) {
            uint4 u0 = *reinterpret_cast<const uint4*>(hlin + (size_t)s0 * HCv + lane * 8);
            float2 f;
            f = __half22float2(*reinterpret_cast<__half2*>(&u0.x)); acc[0] += w0 * f.x; acc[1] += w0 * f.y;
            f = __half22float2(*reinterpret_cast<__half2*>(&u0.y)); acc[2] += w0 * f.x; acc[3] += w0 * f.y;
            f = __half22float2(*reinterpret_cast<__half2*>(&u0.z)); acc[4] += w0 * f.x; acc[5] += w0 * f.y;
            f = __half22float2(*reinterpret_cast<__half2*>(&u0.w)); acc[6] += w0 * f.x; acc[7] += w0 * f.y;
        } else {
            float2 a = __half22float2(*reinterpret_cast<const __half2*>(hlin + (size_t)s0 * HCv + lane * 2));
            acc[0] += w0 * a.x;
            acc[1] += w0 * a.y;
        }
    }

    float inv = 1.0f / (wsum + 1e-16f);
    if (MODE == 0) {
        float r[CPL];
#pragma unroll
        for (int j = 0; j < CPL; j++) {
            int c = lane * CPL + j;
            float v = acc[j] * inv + bias[c];
            v = (v - mean[c]) * rsqrtf(var[c] + EPS_BN) * gamma[c] + beta[c];
            r[j] = (v > 0.f) ? v : 0.f;
        }
        if (CPL == 8) {
            __half2 p0 = __floats2half2_rn(r[0], r[1]);
            __half2 p1 = __floats2half2_rn(r[2], r[3]);
            __half2 p2 = __floats2half2_rn(r[4], r[5]);
            __half2 p3 = __floats2half2_rn(r[6], r[7]);
            uint4 u;
            u.x = *reinterpret_cast<unsigned*>(&p0);
            u.y = *reinterpret_cast<unsigned*>(&p1);
            u.z = *reinterpret_cast<unsigned*>(&p2);
            u.w = *reinterpret_cast<unsigned*>(&p3);
            *reinterpret_cast<uint4*>(out + (size_t)gw * HCv + lane * 8) = u;
        }
    } else {
        // layer 3: bias + ReLU, then mean-pool atomics (CPL == 2)
        int b = __ldg(&batch[gw]);
        float v0 = acc[0] * inv + bias[lane * 2];
        float v1 = acc[1] * inv + bias[lane * 2 + 1];
        v0 = (v0 > 0.f) ? v0 : 0.f;
        v1 = (v1 > 0.f) ? v1 : 0.f;
        atomicAdd(&pooled[b * HC3 + lane * 2], v0);
        atomicAdd(&pooled[b * HC3 + lane * 2 + 1], v1);
        if (lane == 0) atomicAdd(&cnt[b], 1);
    }
}

// ---------------- final MLP ----------------
__global__ void mlp_kernel(const float* __restrict__ pooled, const int* __restrict__ cnt,
                           const float* __restrict__ w1, const float* __restrict__ b1,
                           const float* __restrict__ w2, const float* __restrict__ b2,
                           float* __restrict__ out) {
    int g = blockIdx.x;
    int t = threadIdx.x;
    __shared__ float m[HC3];
    __shared__ float hid[32];
    float c = (float)cnt[g];
    if (c < 1.0f) c = 1.0f;
    m[t] = pooled[g * HC3 + t] / c;
    __syncthreads();
    if (t < 32) {
        float s = b1[t];
#pragma unroll
        for (int k = 0; k < HC3; k++) s += m[k] * w1[k * 32 + t];
        hid[t] = (s > 0.f) ? s : 0.f;
    }
    __syncthreads();
    if (t < NCLASS) {
        float s = b2[t];
#pragma unroll
        for (int k = 0; k < 32; k++) s += hid[k] * w2[k * NCLASS + t];
        out[g * NCLASS + t] = s;
    }
}

// ---------------- host orchestration ----------------
extern "C" void kernel_launch(void* const* d_in, const int* in_sizes, int n_in,
                              void* d_out, int out_size) {
    const float* x     = (const float*)d_in[0];
    const int*   ei    = (const int*)  d_in[1];
    const int*   batch = (const int*)  d_in[2];
    const float* W1    = (const float*)d_in[3];
    const float* a1s   = (const float*)d_in[4];
    const float* a1d   = (const float*)d_in[5];
    const float* b1    = (const float*)d_in[6];
    const float* bn1g  = (const float*)d_in[7];
    const float* bn1b  = (const float*)d_in[8];
    const float* bn1m  = (const float*)d_in[9];
    const float* bn1v  = (const float*)d_in[10];
    const float* W2    = (const float*)d_in[11];
    const float* a2s   = (const float*)d_in[12];
    const float* a2d   = (const float*)d_in[13];
    const float* b2    = (const float*)d_in[14];
    const float* bn2g  = (const float*)d_in[15];
    const float* bn2b  = (const float*)d_in[16];
    const float* bn2m  = (const float*)d_in[17];
    const float* bn2v  = (const float*)d_in[18];
    const float* W3    = (const float*)d_in[19];
    const float* a3s   = (const float*)d_in[20];
    const float* a3d   = (const float*)d_in[21];
    const float* b3    = (const float*)d_in[22];
    const float* lin1w = (const float*)d_in[23];
    const float* lin1b = (const float*)d_in[24];
    const float* lin2w = (const float*)d_in[25];
    const float* lin2b = (const float*)d_in[26];
    float* out = (float*)d_out;

    __half *xh, *hlin, *hagg, *wt;
    float *als, *ald, *pooled;
    int *counts, *rowptr, *csr_src, *bsums, *cnt;
    cudaGetSymbolAddress((void**)&xh,      g_xh);
    cudaGetSymbolAddress((void**)&hlin,    g_hlin);
    cudaGetSymbolAddress((void**)&hagg,    g_hagg);
    cudaGetSymbolAddress((void**)&wt,      g_wt);
    cudaGetSymbolAddress((void**)&als,     g_als);
    cudaGetSymbolAddress((void**)&ald,     g_ald);
    cudaGetSymbolAddress((void**)&pooled,  g_pooled);
    cudaGetSymbolAddress((void**)&counts,  g_counts);
    cudaGetSymbolAddress((void**)&rowptr,  g_rowptr);
    cudaGetSymbolAddress((void**)&csr_src, g_csr_src);
    cudaGetSymbolAddress((void**)&bsums,   g_bsums);
    cudaGetSymbolAddress((void**)&cnt,     g_cnt);

    const int TB = 256;
    const int edgeBlocks = cdiv(ETOT, TB);
    const int nodeWarpBlocks = cdiv(NN * 32, TB);

    // 0: prep (x->fp16, W transpose, zero counters)
    prep_kernel<<<cdiv(XHSZ, TB), TB>>>(x, W1, W2, W3, wt, xh, counts, pooled, cnt);
    // 1-2: CSR histogram + scan
    hist_kernel<<<edgeBlocks, TB>>>(ei, counts);
    scan_pass1<<<NBLK1, 256>>>(counts, rowptr, bsums);
    // 3: layer-1 GEMM (profiled launch index 3)
    {
        dim3 grid(HC12 / 128, cdiv(NN, 128));
        gemm_attn<128, 2, 4, 4><<<grid, 256>>>(xh, wt, hlin, a1s, a1d, als, ald, NN, HC12, FIN);
    }
    // 4-5: finish CSR
    scan_fixup<<<NBLK1, 256>>>(rowptr, bsums);
    scatter_kernel<<<edgeBlocks, TB>>>(ei, rowptr, counts, csr_src);
    // 6: layer-1 aggregate
    gat_aggregate_kernel<HC12, 4, 0><<<nodeWarpBlocks, TB>>>(
        hlin, rowptr, csr_src, als, ald, b1, bn1g, bn1b, bn1m, bn1v, hagg, nullptr, nullptr, nullptr);
    // 7-8: layer 2
    {
        dim3 grid(HC12 / 128, cdiv(NN, 128));
        gemm_attn<128, 2, 4, 4><<<grid, 256>>>(hagg, wt + W1SZ, hlin, a2s, a2d, als, ald, NN, HC12, HC12);
        gat_aggregate_kernel<HC12, 4, 0><<<nodeWarpBlocks, TB>>>(
            hlin, rowptr, csr_src, als, ald, b2, bn2g, bn2b, bn2m, bn2v, hagg, nullptr, nullptr, nullptr);
    }
    // 9-10: layer 3 (aggregate fused with mean-pool)
    {
        dim3 grid(HC3 / 64, cdiv(NN, 128));
        gemm_attn<64, 4, 2, 1><<<grid, 256>>>(hagg, wt + W1SZ + W2SZ, hlin, a3s, a3d, als, ald, NN, HC3, HC12);
        gat_aggregate_kernel<HC3, 1, 1><<<nodeWarpBlocks, TB>>>(
            hlin, rowptr, csr_src, als, ald, b3, nullptr, nullptr, nullptr, nullptr,
            nullptr, batch, pooled, cnt);
    }
    // 11: MLP
    mlp_kernel<<<NGRAPH, HC3>>>(pooled, cnt, lin1w, lin1b, lin2w, lin2b, out);

    (void)in_sizes; (void)n_in; (void)out_size;
}